// round 7
// baseline (speedup 1.0000x reference)
#include <cuda_runtime.h>
#include <cuda_bf16.h>
#include <mma.h>
#include <math.h>
#include <stdint.h>

using namespace nvcuda;

#define BATCH 4
#define NPIX  4096
#define CH    512
#define DQ    64
#define MTOT  (BATCH*NPIX)

// Scratch (device globals: the sanctioned no-alloc workaround)
static __device__ float          g_f[BATCH * NPIX * DQ];
static __device__ float          g_g[BATCH * NPIX * DQ];
static __device__ __nv_bfloat16  g_vh[(size_t)MTOT * CH];          // 16 MB
static __device__ __nv_bfloat16  g_sh[(size_t)BATCH * NPIX * NPIX]; // 128 MB, exp(S) bf16

// ---------------------------------------------------------------------------
// cp.async helpers
// ---------------------------------------------------------------------------
__device__ __forceinline__ void cp_async16(void* smem_dst, const void* gmem_src) {
    uint32_t sa = (uint32_t)__cvta_generic_to_shared(smem_dst);
    asm volatile("cp.async.cg.shared.global [%0], [%1], 16;\n" :: "r"(sa), "l"(gmem_src));
}
__device__ __forceinline__ void cp_commit() {
    asm volatile("cp.async.commit_group;\n");
}
__device__ __forceinline__ void cp_wait_all() {
    asm volatile("cp.async.wait_group 0;\n");
}

__device__ __forceinline__ uint32_t pack_bf162(float lo, float hi) {
    __nv_bfloat162 h = __floats2bfloat162_rn(lo, hi);
    return *reinterpret_cast<uint32_t*>(&h);
}

// ---------------------------------------------------------------------------
// FFMA GEMM for the small f/g projections (N=64): C = A[M,K] @ B[K,64]
// ---------------------------------------------------------------------------
__global__ __launch_bounds__(256)
void gemm_proj(const float* __restrict__ A, const float* __restrict__ B,
               float* __restrict__ C, int M, int N, int K)
{
    __shared__ float As[64][33];
    __shared__ float Bs[32][64];

    const int tx = threadIdx.x, ty = threadIdx.y;
    const int tid = ty * 16 + tx;
    const int bm = blockIdx.y * 64;
    const int bn = blockIdx.x * 64;

    float acc[4][4] = {};

    for (int k0 = 0; k0 < K; k0 += 32) {
        #pragma unroll
        for (int l = 0; l < 8; l++) {
            int idx = tid + l * 256;
            int r = idx >> 5, c = idx & 31;
            As[r][c] = A[(size_t)(bm + r) * K + k0 + c];
        }
        #pragma unroll
        for (int l = 0; l < 8; l++) {
            int idx = tid + l * 256;
            int r = idx >> 6, c = idx & 63;
            Bs[r][c] = B[(size_t)(k0 + r) * N + bn + c];
        }
        __syncthreads();

        #pragma unroll
        for (int kk = 0; kk < 32; kk++) {
            float a[4], b[4];
            #pragma unroll
            for (int i = 0; i < 4; i++) a[i] = As[ty * 4 + i][kk];
            #pragma unroll
            for (int j = 0; j < 4; j++) b[j] = Bs[kk][tx * 4 + j];
            #pragma unroll
            for (int i = 0; i < 4; i++)
                #pragma unroll
                for (int j = 0; j < 4; j++)
                    acc[i][j] += a[i] * b[j];
        }
        __syncthreads();
    }

    #pragma unroll
    for (int i = 0; i < 4; i++)
        #pragma unroll
        for (int j = 0; j < 4; j++)
            C[(size_t)(bm + ty * 4 + i) * N + bn + tx * 4 + j] = acc[i][j];
}

// ---------------------------------------------------------------------------
// v = x @ Wh : TF32 GEMM, 128x128 tile, writes V in bf16 (per-warp staging).
// ---------------------------------------------------------------------------
__global__ __launch_bounds__(256)
void gemm_v(const float* __restrict__ A, const float* __restrict__ B,
            __nv_bfloat16* __restrict__ C)
{
    __shared__ float As[128][36];
    __shared__ float Bs[32][132];
    __shared__ float wscr[8][256];    // per-warp 16x16 stage

    const int tid  = threadIdx.x;
    const int warp = tid >> 5;
    const int lane = tid & 31;
    const int wm   = warp >> 2;
    const int wn   = warp & 3;
    const int bm   = blockIdx.y * 128;
    const int bn   = blockIdx.x * 128;

    wmma::fragment<wmma::accumulator, 16, 16, 8, float> acc[4][2];
    #pragma unroll
    for (int mi = 0; mi < 4; mi++)
        #pragma unroll
        for (int ni = 0; ni < 2; ni++)
            wmma::fill_fragment(acc[mi][ni], 0.0f);

    for (int k0 = 0; k0 < CH; k0 += 32) {
        #pragma unroll
        for (int l = 0; l < 4; l++) {
            int i = tid + l * 256;
            int r = i >> 3, c4 = i & 7;
            *reinterpret_cast<float4*>(&As[r][c4 * 4]) =
                *reinterpret_cast<const float4*>(&A[(size_t)(bm + r) * CH + k0 + c4 * 4]);
        }
        #pragma unroll
        for (int l = 0; l < 4; l++) {
            int i = tid + l * 256;
            int r = i >> 5, c4 = i & 31;
            *reinterpret_cast<float4*>(&Bs[r][c4 * 4]) =
                *reinterpret_cast<const float4*>(&B[(size_t)(k0 + r) * CH + bn + c4 * 4]);
        }
        __syncthreads();

        #pragma unroll
        for (int kk = 0; kk < 32; kk += 8) {
            wmma::fragment<wmma::matrix_a, 16, 16, 8, wmma::precision::tf32, wmma::row_major> af[4];
            wmma::fragment<wmma::matrix_b, 16, 16, 8, wmma::precision::tf32, wmma::row_major> bf[2];
            #pragma unroll
            for (int mi = 0; mi < 4; mi++) {
                wmma::load_matrix_sync(af[mi], &As[wm * 64 + mi * 16][kk], 36);
                #pragma unroll
                for (int e = 0; e < af[mi].num_elements; e++)
                    af[mi].x[e] = wmma::__float_to_tf32(af[mi].x[e]);
            }
            #pragma unroll
            for (int ni = 0; ni < 2; ni++) {
                wmma::load_matrix_sync(bf[ni], &Bs[kk][wn * 32 + ni * 16], 132);
                #pragma unroll
                for (int e = 0; e < bf[ni].num_elements; e++)
                    bf[ni].x[e] = wmma::__float_to_tf32(bf[ni].x[e]);
            }
            #pragma unroll
            for (int mi = 0; mi < 4; mi++)
                #pragma unroll
                for (int ni = 0; ni < 2; ni++)
                    wmma::mma_sync(acc[mi][ni], af[mi], bf[ni], acc[mi][ni]);
        }
        __syncthreads();
    }

    // bf16 epilogue via per-warp scratch
    const int srow = lane >> 1;
    const int shalf = lane & 1;
    #pragma unroll
    for (int mi = 0; mi < 4; mi++)
        #pragma unroll
        for (int ni = 0; ni < 2; ni++) {
            wmma::store_matrix_sync(&wscr[warp][0], acc[mi][ni], 16, wmma::mem_row_major);
            __syncwarp();
            const float* src = &wscr[warp][srow * 16 + shalf * 8];
            uint4 o;
            o.x = pack_bf162(src[0], src[1]);
            o.y = pack_bf162(src[2], src[3]);
            o.z = pack_bf162(src[4], src[5]);
            o.w = pack_bf162(src[6], src[7]);
            __nv_bfloat16* dst = &C[(size_t)(bm + wm * 64 + mi * 16 + srow) * CH
                                    + bn + wn * 32 + ni * 16 + shalf * 8];
            *reinterpret_cast<uint4*>(dst) = o;
            __syncwarp();
        }
}

// ---------------------------------------------------------------------------
// exp(S) = exp(f @ g^T), per batch. 128x128 tile, single K=64 pass.
// Writes UNNORMALIZED exp(s) as bf16 (softmax shift-invariant; s is O(10)).
// ---------------------------------------------------------------------------
#define SE_LD 68
#define SE_STG 132
__global__ __launch_bounds__(256)
void gemm_s_exp()
{
    extern __shared__ float sm_se[];
    float* Fs = sm_se;                 // [128][68]
    float* Gs = sm_se + 128 * SE_LD;   // [128][68]

    const int tid  = threadIdx.x;
    const int warp = tid >> 5;
    const int wm   = warp >> 2;        // 0..1
    const int wn   = warp & 3;         // 0..3
    const int bm   = blockIdx.y * 128;
    const int bn   = blockIdx.x * 128;
    const int b    = blockIdx.z;

    const float* F = g_f + (size_t)b * NPIX * DQ;
    const float* G = g_g + (size_t)b * NPIX * DQ;
    __nv_bfloat16* S = g_sh + (size_t)b * NPIX * NPIX;

    #pragma unroll
    for (int l = 0; l < 8; l++) {
        int i = tid + l * 256;
        int r = i >> 4, c4 = i & 15;
        *reinterpret_cast<float4*>(&Fs[r * SE_LD + c4 * 4]) =
            *reinterpret_cast<const float4*>(&F[(size_t)(bm + r) * DQ + c4 * 4]);
        *reinterpret_cast<float4*>(&Gs[r * SE_LD + c4 * 4]) =
            *reinterpret_cast<const float4*>(&G[(size_t)(bn + r) * DQ + c4 * 4]);
    }
    __syncthreads();

    wmma::fragment<wmma::accumulator, 16, 16, 8, float> acc[4][2];
    #pragma unroll
    for (int mi = 0; mi < 4; mi++)
        #pragma unroll
        for (int ni = 0; ni < 2; ni++)
            wmma::fill_fragment(acc[mi][ni], 0.0f);

    #pragma unroll
    for (int kk = 0; kk < DQ; kk += 8) {
        wmma::fragment<wmma::matrix_a, 16, 16, 8, wmma::precision::tf32, wmma::row_major> af[4];
        wmma::fragment<wmma::matrix_b, 16, 16, 8, wmma::precision::tf32, wmma::col_major> bf[2];
        #pragma unroll
        for (int mi = 0; mi < 4; mi++) {
            wmma::load_matrix_sync(af[mi], &Fs[(wm * 64 + mi * 16) * SE_LD + kk], SE_LD);
            #pragma unroll
            for (int e = 0; e < af[mi].num_elements; e++)
                af[mi].x[e] = wmma::__float_to_tf32(af[mi].x[e]);
        }
        #pragma unroll
        for (int ni = 0; ni < 2; ni++) {
            wmma::load_matrix_sync(bf[ni], &Gs[(wn * 32 + ni * 16) * SE_LD + kk], SE_LD);
            #pragma unroll
            for (int e = 0; e < bf[ni].num_elements; e++)
                bf[ni].x[e] = wmma::__float_to_tf32(bf[ni].x[e]);
        }
        #pragma unroll
        for (int mi = 0; mi < 4; mi++)
            #pragma unroll
            for (int ni = 0; ni < 2; ni++)
                wmma::mma_sync(acc[mi][ni], af[mi], bf[ni], acc[mi][ni]);
    }

    // exp in fragments, stage fp32 tile, convert+store bf16
    const float LOG2E = 1.4426950408889634f;
    #pragma unroll
    for (int mi = 0; mi < 4; mi++)
        #pragma unroll
        for (int ni = 0; ni < 2; ni++)
            #pragma unroll
            for (int e = 0; e < acc[mi][ni].num_elements; e++)
                acc[mi][ni].x[e] = exp2f(acc[mi][ni].x[e] * LOG2E);

    __syncthreads();                // F/G tiles fully consumed -> reuse as stage
    float* stage = sm_se;           // [128][132]
    #pragma unroll
    for (int mi = 0; mi < 4; mi++)
        #pragma unroll
        for (int ni = 0; ni < 2; ni++)
            wmma::store_matrix_sync(&stage[(wm * 64 + mi * 16) * SE_STG + wn * 32 + ni * 16],
                                    acc[mi][ni], SE_STG, wmma::mem_row_major);
    __syncthreads();

    // 128 rows x 16 chunks of 8 bf16 = 2048 chunks, 8 per thread
    #pragma unroll
    for (int l = 0; l < 8; l++) {
        int i = tid + l * 256;
        int r = i >> 4, c = i & 15;
        const float* src = &stage[r * SE_STG + c * 8];
        uint4 o;
        o.x = pack_bf162(src[0], src[1]);
        o.y = pack_bf162(src[2], src[3]);
        o.z = pack_bf162(src[4], src[5]);
        o.w = pack_bf162(src[6], src[7]);
        *reinterpret_cast<uint4*>(&S[(size_t)(bm + r) * NPIX + bn + c * 8]) = o;
    }
}

// ---------------------------------------------------------------------------
// out = gamma * (P @ V) + x, where P = rownorm(exp(S)), all bf16 inputs.
// M-tile 64, N-tile 256 (blockIdx.y selects half), K-tile 64, 256 threads,
// 8 warps (warp tile 64x32). bf16 m16n16k16 wmma, no register spills
// (256 threads -> 256-reg/thread ceiling). 2 blocks/SM (smem 86 KB).
// ---------------------------------------------------------------------------
#define PV_ALD 72
#define PV_BLD 264
#define PV_SLD 260
#define PV_ABUF (64 * PV_ALD)       // bf16 elems per A buffer (4608)
#define PV_BBUF (64 * PV_BLD)       // bf16 elems per B buffer (16896)
#define PV_TILES (NPIX / 64)        // 64

__global__ __launch_bounds__(256, 1)
void gemm_pv(const float* __restrict__ x, const float* __restrict__ gam_p,
             float* __restrict__ out)
{
    extern __shared__ __nv_bfloat16 sm_pv[];
    __nv_bfloat16* As = sm_pv;                        // 2 * 4608
    __nv_bfloat16* Bs = sm_pv + 2 * PV_ABUF;          // 2 * 16896 (reused as f32 stage)
    float* rowsum = reinterpret_cast<float*>(sm_pv + 2 * PV_ABUF + 2 * PV_BBUF); // 64

    const int tid  = threadIdx.x;
    const int warp = tid >> 5;
    const int bm   = blockIdx.x * 64;
    const int nh   = blockIdx.y;           // 0..1 -> channel half
    const int b    = blockIdx.z;
    const int cn0  = nh * 256;

    const __nv_bfloat16* S = g_sh + (size_t)b * NPIX * NPIX;
    const __nv_bfloat16* V = g_vh + (size_t)b * NPIX * CH;

    if (tid < 64) rowsum[tid] = 0.0f;

    // ---- preload tile 0 ----
    {
        // A tile: 64 rows x 8 chunks of 8 bf16 = 512 chunks, 2/thread
        #pragma unroll
        for (int l = 0; l < 2; l++) {
            int i = tid + l * 256;
            int r = i >> 3, c8 = i & 7;
            cp_async16(&As[r * PV_ALD + c8 * 8], &S[(size_t)(bm + r) * NPIX + c8 * 8]);
        }
        // B tile: 64 rows x 32 chunks of 8 = 2048 chunks, 8/thread
        #pragma unroll
        for (int l = 0; l < 8; l++) {
            int i = tid + l * 256;
            int r = i >> 5, c8 = i & 31;
            cp_async16(&Bs[r * PV_BLD + c8 * 8], &V[(size_t)r * CH + cn0 + c8 * 8]);
        }
        cp_commit();
    }
    cp_wait_all();
    __syncthreads();

    wmma::fragment<wmma::accumulator, 16, 16, 16, float> acc[4][2];
    #pragma unroll
    for (int mi = 0; mi < 4; mi++)
        #pragma unroll
        for (int ni = 0; ni < 2; ni++)
            wmma::fill_fragment(acc[mi][ni], 0.0f);

    for (int t = 0; t < PV_TILES; t++) {
        const int cur = t & 1;
        if (t + 1 < PV_TILES) {
            const int nxt = cur ^ 1;
            const int k0 = (t + 1) * 64;
            #pragma unroll
            for (int l = 0; l < 2; l++) {
                int i = tid + l * 256;
                int r = i >> 3, c8 = i & 7;
                cp_async16(&As[nxt * PV_ABUF + r * PV_ALD + c8 * 8],
                           &S[(size_t)(bm + r) * NPIX + k0 + c8 * 8]);
            }
            #pragma unroll
            for (int l = 0; l < 8; l++) {
                int i = tid + l * 256;
                int r = i >> 5, c8 = i & 31;
                cp_async16(&Bs[nxt * PV_BBUF + r * PV_BLD + c8 * 8],
                           &V[(size_t)(k0 + r) * CH + cn0 + c8 * 8]);
            }
            cp_commit();
        }

        // row-sum from the bf16 A tile (2 chunks of 8 per thread)
        #pragma unroll
        for (int l = 0; l < 2; l++) {
            int i = tid + l * 256;
            int r = i >> 3;
            const __nv_bfloat162* a2 = reinterpret_cast<const __nv_bfloat162*>(
                &As[cur * PV_ABUF + r * PV_ALD + (i & 7) * 8]);
            float p = 0.0f;
            #pragma unroll
            for (int q = 0; q < 4; q++) {
                float2 f2 = __bfloat1622float2(a2[q]);
                p += f2.x + f2.y;
            }
            p += __shfl_xor_sync(0xFFFFFFFFu, p, 1);
            p += __shfl_xor_sync(0xFFFFFFFFu, p, 2);
            p += __shfl_xor_sync(0xFFFFFFFFu, p, 4);
            if ((tid & 7) == 0) rowsum[r] += p;
        }

        // MMA on current buffer: K = 64 in 4 steps of 16
        #pragma unroll
        for (int kk = 0; kk < 64; kk += 16) {
            wmma::fragment<wmma::matrix_a, 16, 16, 16, __nv_bfloat16, wmma::row_major> af[4];
            wmma::fragment<wmma::matrix_b, 16, 16, 16, __nv_bfloat16, wmma::row_major> bf[2];
            #pragma unroll
            for (int mi = 0; mi < 4; mi++)
                wmma::load_matrix_sync(af[mi], &As[cur * PV_ABUF + (mi * 16) * PV_ALD + kk], PV_ALD);
            #pragma unroll
            for (int ni = 0; ni < 2; ni++)
                wmma::load_matrix_sync(bf[ni], &Bs[cur * PV_BBUF + kk * PV_BLD + warp * 32 + ni * 16], PV_BLD);
            #pragma unroll
            for (int mi = 0; mi < 4; mi++)
                #pragma unroll
                for (int ni = 0; ni < 2; ni++)
                    wmma::mma_sync(acc[mi][ni], af[mi], bf[ni], acc[mi][ni]);
        }

        if (t + 1 < PV_TILES) {
            cp_wait_all();
            __syncthreads();
        }
    }

    // ---- epilogue: stage (f32, reuse Bs) -> normalize -> gamma -> +x ----
    __syncthreads();
    float* stage = reinterpret_cast<float*>(Bs);   // 64 x 260 f32 = 66560 B (fits in 67584)
    #pragma unroll
    for (int mi = 0; mi < 4; mi++)
        #pragma unroll
        for (int ni = 0; ni < 2; ni++)
            wmma::store_matrix_sync(&stage[(mi * 16) * PV_SLD + warp * 32 + ni * 16],
                                    acc[mi][ni], PV_SLD, wmma::mem_row_major);
    __syncthreads();

    const float gam = gam_p[0];
    // 64 rows x 64 float4-cols = 4096 float4 -> 16 iterations of 256 threads
    #pragma unroll
    for (int l = 0; l < 16; l++) {
        int i = tid + l * 256;
        int r = i >> 6, c4 = i & 63;
        float4 s4 = *reinterpret_cast<float4*>(&stage[r * PV_SLD + c4 * 4]);
        const float sc = gam / rowsum[r];
        size_t gidx = ((size_t)b * NPIX + bm + r) * CH + cn0 + c4 * 4;
        float4 x4 = *reinterpret_cast<const float4*>(&x[gidx]);
        float4 o;
        o.x = s4.x * sc + x4.x;
        o.y = s4.y * sc + x4.y;
        o.z = s4.z * sc + x4.z;
        o.w = s4.w * sc + x4.w;
        *reinterpret_cast<float4*>(&out[gidx]) = o;
    }
}

// ---------------------------------------------------------------------------
extern "C" void kernel_launch(void* const* d_in, const int* in_sizes, int n_in,
                              void* d_out, int out_size)
{
    const float* x     = (const float*)d_in[0];
    const float* wf    = (const float*)d_in[1];
    const float* wg    = (const float*)d_in[2];
    const float* wh    = (const float*)d_in[3];
    const float* gamma = (const float*)d_in[4];
    float* out = (float*)d_out;

    float *pf, *pg;
    __nv_bfloat16* pvh;
    cudaGetSymbolAddress((void**)&pf,  g_f);
    cudaGetSymbolAddress((void**)&pg,  g_g);
    cudaGetSymbolAddress((void**)&pvh, g_vh);

    const int SE_SMEM = 2 * 128 * SE_LD * 4;                          // 69632
    const int PV_SMEM = (2 * PV_ABUF + 2 * PV_BBUF) * 2 + 64 * 4;     // 86272
    static bool attr_done = false;
    if (!attr_done) {
        cudaFuncSetAttribute(gemm_s_exp, cudaFuncAttributeMaxDynamicSharedMemorySize, SE_SMEM);
        cudaFuncSetAttribute(gemm_pv,    cudaFuncAttributeMaxDynamicSharedMemorySize, PV_SMEM);
        attr_done = true;
    }

    // f, g projections (small; FFMA path)
    gemm_proj<<<dim3(1, MTOT / 64), dim3(16, 16)>>>(x, wf, pf, MTOT, DQ, CH);
    gemm_proj<<<dim3(1, MTOT / 64), dim3(16, 16)>>>(x, wg, pg, MTOT, DQ, CH);

    // v = x @ Wh  (bf16 output)
    gemm_v<<<dim3(CH / 128, MTOT / 128), 256>>>(x, wh, pvh);

    // exp(S) = exp(f @ g^T)  (bf16 output)
    gemm_s_exp<<<dim3(NPIX / 128, NPIX / 128, BATCH), 256, SE_SMEM>>>();

    // out = gamma * rownorm(exp(S)) @ V + x
    gemm_pv<<<dim3(NPIX / 64, 2, BATCH), 256, PV_SMEM>>>(x, gamma, out);
}

// round 9
// speedup vs baseline: 1.1033x; 1.1033x over previous
#include <cuda_runtime.h>
#include <cuda_bf16.h>
#include <mma.h>
#include <math.h>
#include <stdint.h>

using namespace nvcuda;

#define BATCH 4
#define NPIX  4096
#define CH    512
#define DQ    64
#define MTOT  (BATCH*NPIX)

// Scratch (device globals: the sanctioned no-alloc workaround)
static __device__ float          g_f[BATCH * NPIX * DQ];
static __device__ float          g_g[BATCH * NPIX * DQ];
static __device__ __nv_bfloat16  g_vh[(size_t)MTOT * CH];          // 16 MB
static __device__ __nv_bfloat16  g_sh[(size_t)BATCH * NPIX * NPIX]; // 128 MB, exp(S) bf16

// ---------------------------------------------------------------------------
// cp.async helpers
// ---------------------------------------------------------------------------
__device__ __forceinline__ void cp_async16(void* smem_dst, const void* gmem_src) {
    uint32_t sa = (uint32_t)__cvta_generic_to_shared(smem_dst);
    asm volatile("cp.async.cg.shared.global [%0], [%1], 16;\n" :: "r"(sa), "l"(gmem_src));
}
__device__ __forceinline__ void cp_commit() {
    asm volatile("cp.async.commit_group;\n");
}
__device__ __forceinline__ void cp_wait_all() {
    asm volatile("cp.async.wait_group 0;\n");
}

__device__ __forceinline__ uint32_t pack_bf162(float lo, float hi) {
    __nv_bfloat162 h = __floats2bfloat162_rn(lo, hi);
    return *reinterpret_cast<uint32_t*>(&h);
}

// ---------------------------------------------------------------------------
// FFMA GEMM for the small f/g projections (N=64): C = A[M,K] @ B[K,64]
// ---------------------------------------------------------------------------
__global__ __launch_bounds__(256)
void gemm_proj(const float* __restrict__ A, const float* __restrict__ B,
               float* __restrict__ C, int M, int N, int K)
{
    __shared__ float As[64][33];
    __shared__ float Bs[32][64];

    const int tx = threadIdx.x, ty = threadIdx.y;
    const int tid = ty * 16 + tx;
    const int bm = blockIdx.y * 64;
    const int bn = blockIdx.x * 64;

    float acc[4][4] = {};

    for (int k0 = 0; k0 < K; k0 += 32) {
        #pragma unroll
        for (int l = 0; l < 8; l++) {
            int idx = tid + l * 256;
            int r = idx >> 5, c = idx & 31;
            As[r][c] = A[(size_t)(bm + r) * K + k0 + c];
        }
        #pragma unroll
        for (int l = 0; l < 8; l++) {
            int idx = tid + l * 256;
            int r = idx >> 6, c = idx & 63;
            Bs[r][c] = B[(size_t)(k0 + r) * N + bn + c];
        }
        __syncthreads();

        #pragma unroll
        for (int kk = 0; kk < 32; kk++) {
            float a[4], b[4];
            #pragma unroll
            for (int i = 0; i < 4; i++) a[i] = As[ty * 4 + i][kk];
            #pragma unroll
            for (int j = 0; j < 4; j++) b[j] = Bs[kk][tx * 4 + j];
            #pragma unroll
            for (int i = 0; i < 4; i++)
                #pragma unroll
                for (int j = 0; j < 4; j++)
                    acc[i][j] += a[i] * b[j];
        }
        __syncthreads();
    }

    #pragma unroll
    for (int i = 0; i < 4; i++)
        #pragma unroll
        for (int j = 0; j < 4; j++)
            C[(size_t)(bm + ty * 4 + i) * N + bn + tx * 4 + j] = acc[i][j];
}

// ---------------------------------------------------------------------------
// v = x @ Wh : TF32 GEMM, 128x128 tile, writes V in bf16 (per-warp staging).
// ---------------------------------------------------------------------------
__global__ __launch_bounds__(256)
void gemm_v(const float* __restrict__ A, const float* __restrict__ B,
            __nv_bfloat16* __restrict__ C)
{
    __shared__ float As[128][36];
    __shared__ float Bs[32][132];
    __shared__ float wscr[8][256];    // per-warp 16x16 stage

    const int tid  = threadIdx.x;
    const int warp = tid >> 5;
    const int lane = tid & 31;
    const int wm   = warp >> 2;
    const int wn   = warp & 3;
    const int bm   = blockIdx.y * 128;
    const int bn   = blockIdx.x * 128;

    wmma::fragment<wmma::accumulator, 16, 16, 8, float> acc[4][2];
    #pragma unroll
    for (int mi = 0; mi < 4; mi++)
        #pragma unroll
        for (int ni = 0; ni < 2; ni++)
            wmma::fill_fragment(acc[mi][ni], 0.0f);

    for (int k0 = 0; k0 < CH; k0 += 32) {
        #pragma unroll
        for (int l = 0; l < 4; l++) {
            int i = tid + l * 256;
            int r = i >> 3, c4 = i & 7;
            *reinterpret_cast<float4*>(&As[r][c4 * 4]) =
                *reinterpret_cast<const float4*>(&A[(size_t)(bm + r) * CH + k0 + c4 * 4]);
        }
        #pragma unroll
        for (int l = 0; l < 4; l++) {
            int i = tid + l * 256;
            int r = i >> 5, c4 = i & 31;
            *reinterpret_cast<float4*>(&Bs[r][c4 * 4]) =
                *reinterpret_cast<const float4*>(&B[(size_t)(k0 + r) * CH + bn + c4 * 4]);
        }
        __syncthreads();

        #pragma unroll
        for (int kk = 0; kk < 32; kk += 8) {
            wmma::fragment<wmma::matrix_a, 16, 16, 8, wmma::precision::tf32, wmma::row_major> af[4];
            wmma::fragment<wmma::matrix_b, 16, 16, 8, wmma::precision::tf32, wmma::row_major> bf[2];
            #pragma unroll
            for (int mi = 0; mi < 4; mi++) {
                wmma::load_matrix_sync(af[mi], &As[wm * 64 + mi * 16][kk], 36);
                #pragma unroll
                for (int e = 0; e < af[mi].num_elements; e++)
                    af[mi].x[e] = wmma::__float_to_tf32(af[mi].x[e]);
            }
            #pragma unroll
            for (int ni = 0; ni < 2; ni++) {
                wmma::load_matrix_sync(bf[ni], &Bs[kk][wn * 32 + ni * 16], 132);
                #pragma unroll
                for (int e = 0; e < bf[ni].num_elements; e++)
                    bf[ni].x[e] = wmma::__float_to_tf32(bf[ni].x[e]);
            }
            #pragma unroll
            for (int mi = 0; mi < 4; mi++)
                #pragma unroll
                for (int ni = 0; ni < 2; ni++)
                    wmma::mma_sync(acc[mi][ni], af[mi], bf[ni], acc[mi][ni]);
        }
        __syncthreads();
    }

    // bf16 epilogue via per-warp scratch
    const int srow = lane >> 1;
    const int shalf = lane & 1;
    #pragma unroll
    for (int mi = 0; mi < 4; mi++)
        #pragma unroll
        for (int ni = 0; ni < 2; ni++) {
            wmma::store_matrix_sync(&wscr[warp][0], acc[mi][ni], 16, wmma::mem_row_major);
            __syncwarp();
            const float* src = &wscr[warp][srow * 16 + shalf * 8];
            uint4 o;
            o.x = pack_bf162(src[0], src[1]);
            o.y = pack_bf162(src[2], src[3]);
            o.z = pack_bf162(src[4], src[5]);
            o.w = pack_bf162(src[6], src[7]);
            __nv_bfloat16* dst = &C[(size_t)(bm + wm * 64 + mi * 16 + srow) * CH
                                    + bn + wn * 32 + ni * 16 + shalf * 8];
            *reinterpret_cast<uint4*>(dst) = o;
            __syncwarp();
        }
}

// ---------------------------------------------------------------------------
// exp(S) = exp(f @ g^T), per batch. 128x128 tile, single K=64 pass.
// Writes UNNORMALIZED exp(s) as bf16 (softmax shift-invariant; s is O(10)).
// ---------------------------------------------------------------------------
#define SE_LD 68
#define SE_STG 132
__global__ __launch_bounds__(256)
void gemm_s_exp()
{
    extern __shared__ float sm_se[];
    float* Fs = sm_se;                 // [128][68]
    float* Gs = sm_se + 128 * SE_LD;   // [128][68]

    const int tid  = threadIdx.x;
    const int warp = tid >> 5;
    const int wm   = warp >> 2;        // 0..1
    const int wn   = warp & 3;         // 0..3
    const int bm   = blockIdx.y * 128;
    const int bn   = blockIdx.x * 128;
    const int b    = blockIdx.z;

    const float* F = g_f + (size_t)b * NPIX * DQ;
    const float* G = g_g + (size_t)b * NPIX * DQ;
    __nv_bfloat16* S = g_sh + (size_t)b * NPIX * NPIX;

    #pragma unroll
    for (int l = 0; l < 8; l++) {
        int i = tid + l * 256;
        int r = i >> 4, c4 = i & 15;
        *reinterpret_cast<float4*>(&Fs[r * SE_LD + c4 * 4]) =
            *reinterpret_cast<const float4*>(&F[(size_t)(bm + r) * DQ + c4 * 4]);
        *reinterpret_cast<float4*>(&Gs[r * SE_LD + c4 * 4]) =
            *reinterpret_cast<const float4*>(&G[(size_t)(bn + r) * DQ + c4 * 4]);
    }
    __syncthreads();

    wmma::fragment<wmma::accumulator, 16, 16, 8, float> acc[4][2];
    #pragma unroll
    for (int mi = 0; mi < 4; mi++)
        #pragma unroll
        for (int ni = 0; ni < 2; ni++)
            wmma::fill_fragment(acc[mi][ni], 0.0f);

    #pragma unroll
    for (int kk = 0; kk < DQ; kk += 8) {
        wmma::fragment<wmma::matrix_a, 16, 16, 8, wmma::precision::tf32, wmma::row_major> af[4];
        wmma::fragment<wmma::matrix_b, 16, 16, 8, wmma::precision::tf32, wmma::col_major> bf[2];
        #pragma unroll
        for (int mi = 0; mi < 4; mi++) {
            wmma::load_matrix_sync(af[mi], &Fs[(wm * 64 + mi * 16) * SE_LD + kk], SE_LD);
            #pragma unroll
            for (int e = 0; e < af[mi].num_elements; e++)
                af[mi].x[e] = wmma::__float_to_tf32(af[mi].x[e]);
        }
        #pragma unroll
        for (int ni = 0; ni < 2; ni++) {
            wmma::load_matrix_sync(bf[ni], &Gs[(wn * 32 + ni * 16) * SE_LD + kk], SE_LD);
            #pragma unroll
            for (int e = 0; e < bf[ni].num_elements; e++)
                bf[ni].x[e] = wmma::__float_to_tf32(bf[ni].x[e]);
        }
        #pragma unroll
        for (int mi = 0; mi < 4; mi++)
            #pragma unroll
            for (int ni = 0; ni < 2; ni++)
                wmma::mma_sync(acc[mi][ni], af[mi], bf[ni], acc[mi][ni]);
    }

    // exp in fragments, stage fp32 tile, convert+store bf16
    const float LOG2E = 1.4426950408889634f;
    #pragma unroll
    for (int mi = 0; mi < 4; mi++)
        #pragma unroll
        for (int ni = 0; ni < 2; ni++)
            #pragma unroll
            for (int e = 0; e < acc[mi][ni].num_elements; e++)
                acc[mi][ni].x[e] = exp2f(acc[mi][ni].x[e] * LOG2E);

    __syncthreads();                // F/G tiles fully consumed -> reuse as stage
    float* stage = sm_se;           // [128][132]
    #pragma unroll
    for (int mi = 0; mi < 4; mi++)
        #pragma unroll
        for (int ni = 0; ni < 2; ni++)
            wmma::store_matrix_sync(&stage[(wm * 64 + mi * 16) * SE_STG + wn * 32 + ni * 16],
                                    acc[mi][ni], SE_STG, wmma::mem_row_major);
    __syncthreads();

    // 128 rows x 16 chunks of 8 bf16 = 2048 chunks, 8 per thread
    #pragma unroll
    for (int l = 0; l < 8; l++) {
        int i = tid + l * 256;
        int r = i >> 4, c = i & 15;
        const float* src = &stage[r * SE_STG + c * 8];
        uint4 o;
        o.x = pack_bf162(src[0], src[1]);
        o.y = pack_bf162(src[2], src[3]);
        o.z = pack_bf162(src[4], src[5]);
        o.w = pack_bf162(src[6], src[7]);
        *reinterpret_cast<uint4*>(&S[(size_t)(bm + r) * NPIX + bn + c * 8]) = o;
    }
}

// ---------------------------------------------------------------------------
// out = gamma * (P @ V) + x, where P = rownorm(exp(S)), all bf16 inputs.
// M-tile 128, N-tile 256, K-tile 64, 512 threads, 16 warps (warp tile 32x64).
// acc = 64 regs/thread -> no spills at the 128-reg/thread cap.
// Direct fragment epilogue (per-warp 16x16 stage) with fused norm+residual.
// ---------------------------------------------------------------------------
#define PV_ALD 72
#define PV_BLD 264
#define PV_ABUF (128 * PV_ALD)      // bf16 elems per A stage (9216)
#define PV_BBUF (64 * PV_BLD)       // bf16 elems per B stage (16896)
#define PV_TILES (NPIX / 64)        // 64

__global__ __launch_bounds__(512, 1)
void gemm_pv(const float* __restrict__ x, const float* __restrict__ gam_p,
             float* __restrict__ out)
{
    extern __shared__ __nv_bfloat16 sm_pv[];
    __nv_bfloat16* As = sm_pv;                        // 2 * 9216
    __nv_bfloat16* Bs = sm_pv + 2 * PV_ABUF;          // 2 * 16896
    float* wscr   = reinterpret_cast<float*>(sm_pv + 2 * PV_ABUF + 2 * PV_BBUF); // 16*272
    float* rowsum = wscr + 16 * 272;                  // 128

    const int tid  = threadIdx.x;
    const int warp = tid >> 5;
    const int lane = tid & 31;
    const int wm   = warp >> 2;            // 0..3 -> row offset wm*32
    const int wn   = warp & 3;             // 0..3 -> col offset wn*64
    const int bm   = blockIdx.x * 128;
    const int nh   = blockIdx.y;           // 0..1 -> channel half
    const int b    = blockIdx.z;
    const int cn0  = nh * 256;

    const __nv_bfloat16* S = g_sh + (size_t)b * NPIX * NPIX;
    const __nv_bfloat16* V = g_vh + (size_t)b * NPIX * CH;

    if (tid < 128) rowsum[tid] = 0.0f;

    // ---- preload tile 0 ----
    {
        // A tile: 128 rows x 8 chunks of 8 bf16 = 1024 chunks, 2/thread
        #pragma unroll
        for (int l = 0; l < 2; l++) {
            int i = tid + l * 512;
            int r = i >> 3, c8 = i & 7;
            cp_async16(&As[r * PV_ALD + c8 * 8], &S[(size_t)(bm + r) * NPIX + c8 * 8]);
        }
        // B tile: 64 rows x 32 chunks of 8 = 2048 chunks, 4/thread
        #pragma unroll
        for (int l = 0; l < 4; l++) {
            int i = tid + l * 512;
            int r = i >> 5, c8 = i & 31;
            cp_async16(&Bs[r * PV_BLD + c8 * 8], &V[(size_t)r * CH + cn0 + c8 * 8]);
        }
        cp_commit();
    }
    cp_wait_all();
    __syncthreads();

    wmma::fragment<wmma::accumulator, 16, 16, 16, float> acc[2][4];
    #pragma unroll
    for (int mi = 0; mi < 2; mi++)
        #pragma unroll
        for (int ni = 0; ni < 4; ni++)
            wmma::fill_fragment(acc[mi][ni], 0.0f);

    for (int t = 0; t < PV_TILES; t++) {
        const int cur = t & 1;
        if (t + 1 < PV_TILES) {
            const int nxt = cur ^ 1;
            const int k0 = (t + 1) * 64;
            #pragma unroll
            for (int l = 0; l < 2; l++) {
                int i = tid + l * 512;
                int r = i >> 3, c8 = i & 7;
                cp_async16(&As[nxt * PV_ABUF + r * PV_ALD + c8 * 8],
                           &S[(size_t)(bm + r) * NPIX + k0 + c8 * 8]);
            }
            #pragma unroll
            for (int l = 0; l < 4; l++) {
                int i = tid + l * 512;
                int r = i >> 5, c8 = i & 31;
                cp_async16(&Bs[nxt * PV_BBUF + r * PV_BLD + c8 * 8],
                           &V[(size_t)(k0 + r) * CH + cn0 + c8 * 8]);
            }
            cp_commit();
        }

        // row-sum from the bf16 A tile (2 chunks of 8 per thread)
        #pragma unroll
        for (int l = 0; l < 2; l++) {
            int i = tid + l * 512;
            int r = i >> 3;
            const __nv_bfloat162* a2 = reinterpret_cast<const __nv_bfloat162*>(
                &As[cur * PV_ABUF + r * PV_ALD + (i & 7) * 8]);
            float p = 0.0f;
            #pragma unroll
            for (int q = 0; q < 4; q++) {
                float2 f2 = __bfloat1622float2(a2[q]);
                p += f2.x + f2.y;
            }
            p += __shfl_xor_sync(0xFFFFFFFFu, p, 1);
            p += __shfl_xor_sync(0xFFFFFFFFu, p, 2);
            p += __shfl_xor_sync(0xFFFFFFFFu, p, 4);
            if ((tid & 7) == 0) rowsum[r] += p;
        }

        // MMA on current buffer: K = 64 in 4 steps of 16; warp tile 32x64
        #pragma unroll
        for (int kk = 0; kk < 64; kk += 16) {
            wmma::fragment<wmma::matrix_a, 16, 16, 16, __nv_bfloat16, wmma::row_major> af[2];
            wmma::fragment<wmma::matrix_b, 16, 16, 16, __nv_bfloat16, wmma::row_major> bf[4];
            #pragma unroll
            for (int mi = 0; mi < 2; mi++)
                wmma::load_matrix_sync(af[mi],
                    &As[cur * PV_ABUF + (wm * 32 + mi * 16) * PV_ALD + kk], PV_ALD);
            #pragma unroll
            for (int ni = 0; ni < 4; ni++)
                wmma::load_matrix_sync(bf[ni],
                    &Bs[cur * PV_BBUF + kk * PV_BLD + wn * 64 + ni * 16], PV_BLD);
            #pragma unroll
            for (int mi = 0; mi < 2; mi++)
                #pragma unroll
                for (int ni = 0; ni < 4; ni++)
                    wmma::mma_sync(acc[mi][ni], af[mi], bf[ni], acc[mi][ni]);
        }

        if (t + 1 < PV_TILES) {
            cp_wait_all();
            __syncthreads();
        }
    }

    // ---- epilogue: per-warp fragment stage -> normalize -> gamma -> +x ----
    __syncthreads();   // rowsum complete & visible to all warps
    const float gam = gam_p[0];
    float* wp = &wscr[warp * 272];
    const int srow = lane >> 1;
    const int half = lane & 1;

    #pragma unroll
    for (int mi = 0; mi < 2; mi++)
        #pragma unroll
        for (int ni = 0; ni < 4; ni++) {
            wmma::store_matrix_sync(wp, acc[mi][ni], 16, wmma::mem_row_major);
            __syncwarp();
            const int r = wm * 32 + mi * 16 + srow;
            const float sc = gam / rowsum[r];
            const float* sp = &wp[srow * 16 + half * 8];
            size_t gidx = ((size_t)b * NPIX + bm + r) * CH
                          + cn0 + wn * 64 + ni * 16 + half * 8;
            float4 x1 = *reinterpret_cast<const float4*>(&x[gidx]);
            float4 x2 = *reinterpret_cast<const float4*>(&x[gidx + 4]);
            float4 o1, o2;
            o1.x = sp[0] * sc + x1.x;  o1.y = sp[1] * sc + x1.y;
            o1.z = sp[2] * sc + x1.z;  o1.w = sp[3] * sc + x1.w;
            o2.x = sp[4] * sc + x2.x;  o2.y = sp[5] * sc + x2.y;
            o2.z = sp[6] * sc + x2.z;  o2.w = sp[7] * sc + x2.w;
            *reinterpret_cast<float4*>(&out[gidx])     = o1;
            *reinterpret_cast<float4*>(&out[gidx + 4]) = o2;
            __syncwarp();
        }
}

// ---------------------------------------------------------------------------
extern "C" void kernel_launch(void* const* d_in, const int* in_sizes, int n_in,
                              void* d_out, int out_size)
{
    const float* x     = (const float*)d_in[0];
    const float* wf    = (const float*)d_in[1];
    const float* wg    = (const float*)d_in[2];
    const float* wh    = (const float*)d_in[3];
    const float* gamma = (const float*)d_in[4];
    float* out = (float*)d_out;

    float *pf, *pg;
    __nv_bfloat16* pvh;
    cudaGetSymbolAddress((void**)&pf,  g_f);
    cudaGetSymbolAddress((void**)&pg,  g_g);
    cudaGetSymbolAddress((void**)&pvh, g_vh);

    const int SE_SMEM = 2 * 128 * SE_LD * 4;                                   // 69632
    const int PV_SMEM = (2 * PV_ABUF + 2 * PV_BBUF) * 2 + (16 * 272 + 128) * 4; // 122368
    static bool attr_done = false;
    if (!attr_done) {
        cudaFuncSetAttribute(gemm_s_exp, cudaFuncAttributeMaxDynamicSharedMemorySize, SE_SMEM);
        cudaFuncSetAttribute(gemm_pv,    cudaFuncAttributeMaxDynamicSharedMemorySize, PV_SMEM);
        attr_done = true;
    }

    // f, g projections (small; FFMA path)
    gemm_proj<<<dim3(1, MTOT / 64), dim3(16, 16)>>>(x, wf, pf, MTOT, DQ, CH);
    gemm_proj<<<dim3(1, MTOT / 64), dim3(16, 16)>>>(x, wg, pg, MTOT, DQ, CH);

    // v = x @ Wh  (bf16 output)
    gemm_v<<<dim3(CH / 128, MTOT / 128), 256>>>(x, wh, pvh);

    // exp(S) = exp(f @ g^T)  (bf16 output)
    gemm_s_exp<<<dim3(NPIX / 128, NPIX / 128, BATCH), 256, SE_SMEM>>>();

    // out = gamma * rownorm(exp(S)) @ V + x
    gemm_pv<<<dim3(NPIX / 128, 2, BATCH), 512, PV_SMEM>>>(x, gamma, out);
}

// round 10
// speedup vs baseline: 1.3508x; 1.2243x over previous
#include <cuda_runtime.h>
#include <cuda_bf16.h>
#include <mma.h>
#include <math.h>
#include <stdint.h>

using namespace nvcuda;

#define BATCH 4
#define NPIX  4096
#define CH    512
#define DQ    64
#define MTOT  (BATCH*NPIX)

// Scratch (device globals: the sanctioned no-alloc workaround)
static __device__ __nv_bfloat16  g_fh[MTOT * DQ];                   // bf16 f
static __device__ __nv_bfloat16  g_gh[MTOT * DQ];                   // bf16 g
static __device__ __nv_bfloat16  g_vh[(size_t)MTOT * CH];           // 16 MB
static __device__ __nv_bfloat16  g_sh[(size_t)BATCH * NPIX * NPIX]; // 128 MB exp(S)
static __device__ float          g_rsum[MTOT];                      // row sums

// ---------------------------------------------------------------------------
// cp.async helpers
// ---------------------------------------------------------------------------
__device__ __forceinline__ void cp_async16(void* smem_dst, const void* gmem_src) {
    uint32_t sa = (uint32_t)__cvta_generic_to_shared(smem_dst);
    asm volatile("cp.async.cg.shared.global [%0], [%1], 16;\n" :: "r"(sa), "l"(gmem_src));
}
__device__ __forceinline__ void cp_commit() {
    asm volatile("cp.async.commit_group;\n");
}
__device__ __forceinline__ void cp_wait_all() {
    asm volatile("cp.async.wait_group 0;\n");
}
__device__ __forceinline__ void cp_wait_1() {
    asm volatile("cp.async.wait_group 1;\n");
}

__device__ __forceinline__ uint32_t pack_bf162(float lo, float hi) {
    __nv_bfloat162 h = __floats2bfloat162_rn(lo, hi);
    return *reinterpret_cast<uint32_t*>(&h);
}

// ---------------------------------------------------------------------------
// zero g_rsum
// ---------------------------------------------------------------------------
__global__ void zero_rsum()
{
    g_rsum[blockIdx.x * 1024 + threadIdx.x] = 0.0f;
}

// ---------------------------------------------------------------------------
// FFMA GEMM for the small f/g projections (N=64): C = A[M,K] @ B[K,64], bf16 out
// ---------------------------------------------------------------------------
__global__ __launch_bounds__(256)
void gemm_proj(const float* __restrict__ A, const float* __restrict__ B,
               __nv_bfloat16* __restrict__ C, int M, int N, int K)
{
    __shared__ float As[64][33];
    __shared__ float Bs[32][64];

    const int tx = threadIdx.x, ty = threadIdx.y;
    const int tid = ty * 16 + tx;
    const int bm = blockIdx.y * 64;
    const int bn = blockIdx.x * 64;

    float acc[4][4] = {};

    for (int k0 = 0; k0 < K; k0 += 32) {
        #pragma unroll
        for (int l = 0; l < 8; l++) {
            int idx = tid + l * 256;
            int r = idx >> 5, c = idx & 31;
            As[r][c] = A[(size_t)(bm + r) * K + k0 + c];
        }
        #pragma unroll
        for (int l = 0; l < 8; l++) {
            int idx = tid + l * 256;
            int r = idx >> 6, c = idx & 63;
            Bs[r][c] = B[(size_t)(k0 + r) * N + bn + c];
        }
        __syncthreads();

        #pragma unroll
        for (int kk = 0; kk < 32; kk++) {
            float a[4], b[4];
            #pragma unroll
            for (int i = 0; i < 4; i++) a[i] = As[ty * 4 + i][kk];
            #pragma unroll
            for (int j = 0; j < 4; j++) b[j] = Bs[kk][tx * 4 + j];
            #pragma unroll
            for (int i = 0; i < 4; i++)
                #pragma unroll
                for (int j = 0; j < 4; j++)
                    acc[i][j] += a[i] * b[j];
        }
        __syncthreads();
    }

    #pragma unroll
    for (int i = 0; i < 4; i++) {
        uint2 o;
        o.x = pack_bf162(acc[i][0], acc[i][1]);
        o.y = pack_bf162(acc[i][2], acc[i][3]);
        *reinterpret_cast<uint2*>(&C[(size_t)(bm + ty * 4 + i) * N + bn + tx * 4]) = o;
    }
}

// ---------------------------------------------------------------------------
// v = x @ Wh : TF32 GEMM, 128x128 tile, writes V in bf16 (per-warp staging).
// ---------------------------------------------------------------------------
__global__ __launch_bounds__(256)
void gemm_v(const float* __restrict__ A, const float* __restrict__ B,
            __nv_bfloat16* __restrict__ C)
{
    __shared__ float As[128][36];
    __shared__ float Bs[32][132];
    __shared__ float wscr[8][256];    // per-warp 16x16 stage

    const int tid  = threadIdx.x;
    const int warp = tid >> 5;
    const int lane = tid & 31;
    const int wm   = warp >> 2;
    const int wn   = warp & 3;
    const int bm   = blockIdx.y * 128;
    const int bn   = blockIdx.x * 128;

    wmma::fragment<wmma::accumulator, 16, 16, 8, float> acc[4][2];
    #pragma unroll
    for (int mi = 0; mi < 4; mi++)
        #pragma unroll
        for (int ni = 0; ni < 2; ni++)
            wmma::fill_fragment(acc[mi][ni], 0.0f);

    for (int k0 = 0; k0 < CH; k0 += 32) {
        #pragma unroll
        for (int l = 0; l < 4; l++) {
            int i = tid + l * 256;
            int r = i >> 3, c4 = i & 7;
            *reinterpret_cast<float4*>(&As[r][c4 * 4]) =
                *reinterpret_cast<const float4*>(&A[(size_t)(bm + r) * CH + k0 + c4 * 4]);
        }
        #pragma unroll
        for (int l = 0; l < 4; l++) {
            int i = tid + l * 256;
            int r = i >> 5, c4 = i & 31;
            *reinterpret_cast<float4*>(&Bs[r][c4 * 4]) =
                *reinterpret_cast<const float4*>(&B[(size_t)(k0 + r) * CH + bn + c4 * 4]);
        }
        __syncthreads();

        #pragma unroll
        for (int kk = 0; kk < 32; kk += 8) {
            wmma::fragment<wmma::matrix_a, 16, 16, 8, wmma::precision::tf32, wmma::row_major> af[4];
            wmma::fragment<wmma::matrix_b, 16, 16, 8, wmma::precision::tf32, wmma::row_major> bf[2];
            #pragma unroll
            for (int mi = 0; mi < 4; mi++) {
                wmma::load_matrix_sync(af[mi], &As[wm * 64 + mi * 16][kk], 36);
                #pragma unroll
                for (int e = 0; e < af[mi].num_elements; e++)
                    af[mi].x[e] = wmma::__float_to_tf32(af[mi].x[e]);
            }
            #pragma unroll
            for (int ni = 0; ni < 2; ni++) {
                wmma::load_matrix_sync(bf[ni], &Bs[kk][wn * 32 + ni * 16], 132);
                #pragma unroll
                for (int e = 0; e < bf[ni].num_elements; e++)
                    bf[ni].x[e] = wmma::__float_to_tf32(bf[ni].x[e]);
            }
            #pragma unroll
            for (int mi = 0; mi < 4; mi++)
                #pragma unroll
                for (int ni = 0; ni < 2; ni++)
                    wmma::mma_sync(acc[mi][ni], af[mi], bf[ni], acc[mi][ni]);
        }
        __syncthreads();
    }

    // bf16 epilogue via per-warp scratch
    const int srow = lane >> 1;
    const int shalf = lane & 1;
    #pragma unroll
    for (int mi = 0; mi < 4; mi++)
        #pragma unroll
        for (int ni = 0; ni < 2; ni++) {
            wmma::store_matrix_sync(&wscr[warp][0], acc[mi][ni], 16, wmma::mem_row_major);
            __syncwarp();
            const float* src = &wscr[warp][srow * 16 + shalf * 8];
            uint4 o;
            o.x = pack_bf162(src[0], src[1]);
            o.y = pack_bf162(src[2], src[3]);
            o.z = pack_bf162(src[4], src[5]);
            o.w = pack_bf162(src[6], src[7]);
            __nv_bfloat16* dst = &C[(size_t)(bm + wm * 64 + mi * 16 + srow) * CH
                                    + bn + wn * 32 + ni * 16 + shalf * 8];
            *reinterpret_cast<uint4*>(dst) = o;
            __syncwarp();
        }
}

// ---------------------------------------------------------------------------
// exp(S) = exp(f @ g^T), per batch — bf16 MMA (m16n16k16), no conversions.
// 128x128 tile, K=64 in 4 steps. Epilogue: per-warp stage -> bf16 store +
// f32 row-sum partials atomically accumulated into g_rsum.
// Dynamic smem: Fh[128][72] + Gh[128][72] bf16 + wscr[8][272] f32 = 45568 B.
// ---------------------------------------------------------------------------
#define SE_LDH 72
__global__ __launch_bounds__(256)
void gemm_s_exp()
{
    extern __shared__ uint8_t sm_raw[];
    __nv_bfloat16* Fh = reinterpret_cast<__nv_bfloat16*>(sm_raw);               // 128*72
    __nv_bfloat16* Gh = Fh + 128 * SE_LDH;                                      // 128*72
    float* wscr = reinterpret_cast<float*>(sm_raw + 2 * 128 * SE_LDH * 2);      // 8*272

    const int tid  = threadIdx.x;
    const int warp = tid >> 5;
    const int lane = tid & 31;
    const int wm   = warp >> 2;        // 0..1 -> rows wm*64
    const int wn   = warp & 3;         // 0..3 -> cols wn*32
    const int bm   = blockIdx.y * 128;
    const int bn   = blockIdx.x * 128;
    const int b    = blockIdx.z;

    const __nv_bfloat16* F = g_fh + ((size_t)b * NPIX + bm) * DQ;
    const __nv_bfloat16* G = g_gh + ((size_t)b * NPIX + bn) * DQ;
    __nv_bfloat16* S = g_sh + (size_t)b * NPIX * NPIX;

    // Load F/G tiles: 128 rows x 8 chunks of 8 bf16 = 1024 chunks, 4/thread each
    #pragma unroll
    for (int l = 0; l < 4; l++) {
        int i = tid + l * 256;
        int r = i >> 3, c8 = i & 7;
        *reinterpret_cast<uint4*>(&Fh[r * SE_LDH + c8 * 8]) =
            *reinterpret_cast<const uint4*>(&F[(size_t)r * DQ + c8 * 8]);
        *reinterpret_cast<uint4*>(&Gh[r * SE_LDH + c8 * 8]) =
            *reinterpret_cast<const uint4*>(&G[(size_t)r * DQ + c8 * 8]);
    }
    __syncthreads();

    wmma::fragment<wmma::accumulator, 16, 16, 16, float> acc[4][2];
    #pragma unroll
    for (int mi = 0; mi < 4; mi++)
        #pragma unroll
        for (int ni = 0; ni < 2; ni++)
            wmma::fill_fragment(acc[mi][ni], 0.0f);

    #pragma unroll
    for (int kk = 0; kk < DQ; kk += 16) {
        wmma::fragment<wmma::matrix_a, 16, 16, 16, __nv_bfloat16, wmma::row_major> af[4];
        wmma::fragment<wmma::matrix_b, 16, 16, 16, __nv_bfloat16, wmma::col_major> bf[2];
        #pragma unroll
        for (int mi = 0; mi < 4; mi++)
            wmma::load_matrix_sync(af[mi], &Fh[(wm * 64 + mi * 16) * SE_LDH + kk], SE_LDH);
        #pragma unroll
        for (int ni = 0; ni < 2; ni++)
            wmma::load_matrix_sync(bf[ni], &Gh[(wn * 32 + ni * 16) * SE_LDH + kk], SE_LDH);
        #pragma unroll
        for (int mi = 0; mi < 4; mi++)
            #pragma unroll
            for (int ni = 0; ni < 2; ni++)
                wmma::mma_sync(acc[mi][ni], af[mi], bf[ni], acc[mi][ni]);
    }

    // exp on fragments, then per-warp stage -> bf16 store + rowsum atomics
    const float LOG2E = 1.4426950408889634f;
    #pragma unroll
    for (int mi = 0; mi < 4; mi++)
        #pragma unroll
        for (int ni = 0; ni < 2; ni++)
            #pragma unroll
            for (int e = 0; e < acc[mi][ni].num_elements; e++)
                acc[mi][ni].x[e] = exp2f(acc[mi][ni].x[e] * LOG2E);

    float* wp = &wscr[warp * 272];
    const int srow = lane >> 1;
    const int half = lane & 1;
    #pragma unroll
    for (int mi = 0; mi < 4; mi++) {
        float rpart = 0.0f;
        #pragma unroll
        for (int ni = 0; ni < 2; ni++) {
            wmma::store_matrix_sync(wp, acc[mi][ni], 16, wmma::mem_row_major);
            __syncwarp();
            const float* sp = &wp[srow * 16 + half * 8];
            rpart += sp[0] + sp[1] + sp[2] + sp[3] + sp[4] + sp[5] + sp[6] + sp[7];
            uint4 o;
            o.x = pack_bf162(sp[0], sp[1]);
            o.y = pack_bf162(sp[2], sp[3]);
            o.z = pack_bf162(sp[4], sp[5]);
            o.w = pack_bf162(sp[6], sp[7]);
            *reinterpret_cast<uint4*>(
                &S[(size_t)(bm + wm * 64 + mi * 16 + srow) * NPIX
                   + bn + wn * 32 + ni * 16 + half * 8]) = o;
            __syncwarp();
        }
        rpart += __shfl_xor_sync(0xFFFFFFFFu, rpart, 1);
        if (half == 0)
            atomicAdd(&g_rsum[b * NPIX + bm + wm * 64 + mi * 16 + srow], rpart);
    }
}

// ---------------------------------------------------------------------------
// out = gamma * (P @ V) + x. M-tile 128, N-tile 256, K-tile 64, 512 threads,
// 16 warps (warp tile 32x64). 3-stage cp.async pipeline. Row sums from g_rsum.
// ---------------------------------------------------------------------------
#define PV_ALD 72
#define PV_BLD 264
#define PV_ABUF (128 * PV_ALD)      // bf16 elems per A stage (9216)
#define PV_BBUF (64 * PV_BLD)       // bf16 elems per B stage (16896)
#define PV_TILES (NPIX / 64)        // 64
#define PV_SMEM ((3 * PV_ABUF + 3 * PV_BBUF) * 2 + 16 * 272 * 4)   // 174080

__global__ __launch_bounds__(512, 1)
void gemm_pv(const float* __restrict__ x, const float* __restrict__ gam_p,
             float* __restrict__ out)
{
    extern __shared__ __nv_bfloat16 sm_pv[];
    __nv_bfloat16* As = sm_pv;                        // 3 * 9216
    __nv_bfloat16* Bs = sm_pv + 3 * PV_ABUF;          // 3 * 16896
    float* wscr = reinterpret_cast<float*>(sm_pv + 3 * PV_ABUF + 3 * PV_BBUF);

    const int tid  = threadIdx.x;
    const int warp = tid >> 5;
    const int lane = tid & 31;
    const int wm   = warp >> 2;            // 0..3 -> row offset wm*32
    const int wn   = warp & 3;             // 0..3 -> col offset wn*64
    const int bm   = blockIdx.x * 128;
    const int nh   = blockIdx.y;           // 0..1 -> channel half
    const int b    = blockIdx.z;
    const int cn0  = nh * 256;

    const __nv_bfloat16* S = g_sh + (size_t)b * NPIX * NPIX;
    const __nv_bfloat16* V = g_vh + (size_t)b * NPIX * CH;

    // loaders
    auto load_stage = [&](int buf, int k0) {
        #pragma unroll
        for (int l = 0; l < 2; l++) {
            int i = tid + l * 512;
            int r = i >> 3, c8 = i & 7;
            cp_async16(&As[buf * PV_ABUF + r * PV_ALD + c8 * 8],
                       &S[(size_t)(bm + r) * NPIX + k0 + c8 * 8]);
        }
        #pragma unroll
        for (int l = 0; l < 4; l++) {
            int i = tid + l * 512;
            int r = i >> 5, c8 = i & 31;
            cp_async16(&Bs[buf * PV_BBUF + r * PV_BLD + c8 * 8],
                       &V[(size_t)(k0 + r) * CH + cn0 + c8 * 8]);
        }
        cp_commit();
    };

    // preload stages 0 and 1
    load_stage(0, 0);
    load_stage(1, 64);
    cp_wait_1();          // stage 0 complete
    __syncthreads();

    wmma::fragment<wmma::accumulator, 16, 16, 16, float> acc[2][4];
    #pragma unroll
    for (int mi = 0; mi < 2; mi++)
        #pragma unroll
        for (int ni = 0; ni < 4; ni++)
            wmma::fill_fragment(acc[mi][ni], 0.0f);

    for (int t = 0; t < PV_TILES; t++) {
        const int cur = t % 3;
        if (t + 2 < PV_TILES)
            load_stage((t + 2) % 3, (t + 2) * 64);

        // MMA on current buffer: K = 64 in 4 steps of 16; warp tile 32x64
        #pragma unroll
        for (int kk = 0; kk < 64; kk += 16) {
            wmma::fragment<wmma::matrix_a, 16, 16, 16, __nv_bfloat16, wmma::row_major> af[2];
            wmma::fragment<wmma::matrix_b, 16, 16, 16, __nv_bfloat16, wmma::row_major> bf[4];
            #pragma unroll
            for (int mi = 0; mi < 2; mi++)
                wmma::load_matrix_sync(af[mi],
                    &As[cur * PV_ABUF + (wm * 32 + mi * 16) * PV_ALD + kk], PV_ALD);
            #pragma unroll
            for (int ni = 0; ni < 4; ni++)
                wmma::load_matrix_sync(bf[ni],
                    &Bs[cur * PV_BBUF + kk * PV_BLD + wn * 64 + ni * 16], PV_BLD);
            #pragma unroll
            for (int mi = 0; mi < 2; mi++)
                #pragma unroll
                for (int ni = 0; ni < 4; ni++)
                    wmma::mma_sync(acc[mi][ni], af[mi], bf[ni], acc[mi][ni]);
        }

        if (t + 1 < PV_TILES) {
            if (t + 2 < PV_TILES) cp_wait_1();   // stage t+1 complete (t+2 may fly)
            else                  cp_wait_all(); // last stage
            __syncthreads();
        }
    }

    // ---- epilogue: per-warp fragment stage -> normalize -> gamma -> +x ----
    __syncthreads();
    const float gam = gam_p[0];
    float* wp = &wscr[warp * 272];
    const int srow = lane >> 1;
    const int half = lane & 1;

    #pragma unroll
    for (int mi = 0; mi < 2; mi++)
        #pragma unroll
        for (int ni = 0; ni < 4; ni++) {
            wmma::store_matrix_sync(wp, acc[mi][ni], 16, wmma::mem_row_major);
            __syncwarp();
            const int r = wm * 32 + mi * 16 + srow;
            const float sc = gam / g_rsum[b * NPIX + bm + r];
            const float* sp = &wp[srow * 16 + half * 8];
            size_t gidx = ((size_t)b * NPIX + bm + r) * CH
                          + cn0 + wn * 64 + ni * 16 + half * 8;
            float4 x1 = *reinterpret_cast<const float4*>(&x[gidx]);
            float4 x2 = *reinterpret_cast<const float4*>(&x[gidx + 4]);
            float4 o1, o2;
            o1.x = sp[0] * sc + x1.x;  o1.y = sp[1] * sc + x1.y;
            o1.z = sp[2] * sc + x1.z;  o1.w = sp[3] * sc + x1.w;
            o2.x = sp[4] * sc + x2.x;  o2.y = sp[5] * sc + x2.y;
            o2.z = sp[6] * sc + x2.z;  o2.w = sp[7] * sc + x2.w;
            *reinterpret_cast<float4*>(&out[gidx])     = o1;
            *reinterpret_cast<float4*>(&out[gidx + 4]) = o2;
            __syncwarp();
        }
}

// ---------------------------------------------------------------------------
extern "C" void kernel_launch(void* const* d_in, const int* in_sizes, int n_in,
                              void* d_out, int out_size)
{
    const float* x     = (const float*)d_in[0];
    const float* wf    = (const float*)d_in[1];
    const float* wg    = (const float*)d_in[2];
    const float* wh    = (const float*)d_in[3];
    const float* gamma = (const float*)d_in[4];
    float* out = (float*)d_out;

    __nv_bfloat16 *pfh, *pgh, *pvh;
    cudaGetSymbolAddress((void**)&pfh, g_fh);
    cudaGetSymbolAddress((void**)&pgh, g_gh);
    cudaGetSymbolAddress((void**)&pvh, g_vh);

    const int SE_SMEM = 2 * 128 * SE_LDH * 2 + 8 * 272 * 4;   // 45568
    static bool attr_done = false;
    if (!attr_done) {
        cudaFuncSetAttribute(gemm_s_exp, cudaFuncAttributeMaxDynamicSharedMemorySize, SE_SMEM);
        cudaFuncSetAttribute(gemm_pv,    cudaFuncAttributeMaxDynamicSharedMemorySize, PV_SMEM);
        attr_done = true;
    }

    // zero rowsum accumulator
    zero_rsum<<<MTOT / 1024, 1024>>>();

    // f, g projections (bf16 outputs)
    gemm_proj<<<dim3(1, MTOT / 64), dim3(16, 16)>>>(x, wf, pfh, MTOT, DQ, CH);
    gemm_proj<<<dim3(1, MTOT / 64), dim3(16, 16)>>>(x, wg, pgh, MTOT, DQ, CH);

    // v = x @ Wh  (bf16 output)
    gemm_v<<<dim3(CH / 128, MTOT / 128), 256>>>(x, wh, pvh);

    // exp(S) = exp(f @ g^T)  (bf16 MMA + output, rowsum atomics)
    gemm_s_exp<<<dim3(NPIX / 128, NPIX / 128, BATCH), 256, SE_SMEM>>>();

    // out = gamma * rownorm(exp(S)) @ V + x
    gemm_pv<<<dim3(NPIX / 128, 2, BATCH), 512, PV_SMEM>>>(x, gamma, out);
}

// round 12
// speedup vs baseline: 1.7974x; 1.3306x over previous
#include <cuda_runtime.h>
#include <cuda_bf16.h>
#include <mma.h>
#include <math.h>
#include <stdint.h>

using namespace nvcuda;

#define BATCH 4
#define NPIX  4096
#define CH    512
#define DQ    64
#define MTOT  (BATCH*NPIX)

// Scratch (device globals: the sanctioned no-alloc workaround)
static __device__ __nv_bfloat16  g_xh[(size_t)MTOT * CH];           // bf16 x (16 MB)
static __device__ __nv_bfloat16  g_whh[CH * CH];                    // bf16 Wh
static __device__ __nv_bfloat16  g_wfg[CH * 2 * DQ];                // bf16 [Wf|Wg] 512x128
static __device__ __nv_bfloat16  g_fgh[MTOT * 2 * DQ];              // bf16 [f|g] (4 MB)
static __device__ __nv_bfloat16  g_vh[(size_t)MTOT * CH];           // 16 MB
static __device__ __nv_bfloat16  g_sh[(size_t)BATCH * NPIX * NPIX]; // 128 MB exp(S)
static __device__ float          g_rsum[MTOT];                      // row sums

// ---------------------------------------------------------------------------
// cp.async helpers
// ---------------------------------------------------------------------------
__device__ __forceinline__ void cp_async16(void* smem_dst, const void* gmem_src) {
    uint32_t sa = (uint32_t)__cvta_generic_to_shared(smem_dst);
    asm volatile("cp.async.cg.shared.global [%0], [%1], 16;\n" :: "r"(sa), "l"(gmem_src));
}
__device__ __forceinline__ void cp_commit() {
    asm volatile("cp.async.commit_group;\n");
}
__device__ __forceinline__ void cp_wait_all() {
    asm volatile("cp.async.wait_group 0;\n");
}
__device__ __forceinline__ void cp_wait_1() {
    asm volatile("cp.async.wait_group 1;\n");
}

__device__ __forceinline__ uint32_t pack_bf162(float lo, float hi) {
    __nv_bfloat162 h = __floats2bfloat162_rn(lo, hi);
    return *reinterpret_cast<uint32_t*>(&h);
}

// ---------------------------------------------------------------------------
// small prep kernels
// ---------------------------------------------------------------------------
__global__ void zero_rsum()
{
    g_rsum[blockIdx.x * 1024 + threadIdx.x] = 0.0f;
}

// float -> bf16, 4 elems per thread (n divisible by 256*4)
__global__ void cvt_f32_bf16(const float* __restrict__ src, __nv_bfloat16* __restrict__ dst)
{
    const size_t i = (size_t)blockIdx.x * 256 + threadIdx.x;
    float4 v = reinterpret_cast<const float4*>(src)[i];
    uint2 o;
    o.x = pack_bf162(v.x, v.y);
    o.y = pack_bf162(v.z, v.w);
    reinterpret_cast<uint2*>(dst)[i] = o;
}

// build Wfg[512][128] = [Wf | Wg] in bf16 (device-side symbol access)
__global__ void build_wfg(const float* __restrict__ wf, const float* __restrict__ wg)
{
    const int i = blockIdx.x * 256 + threadIdx.x;   // 0 .. 512*64-1
    const int r = i >> 6, c = i & 63;
    g_wfg[r * 128 + c]      = __float2bfloat16(wf[r * 64 + c]);
    g_wfg[r * 128 + 64 + c] = __float2bfloat16(wg[r * 64 + c]);
}

// ---------------------------------------------------------------------------
// Generic bf16 GEMM: C[M,N] = A[M,K] @ B[K,N], all bf16, fp32 accum.
// Block tile 128x128, K-tile 64, 256 threads, 8 warps (2x4), warp tile 64x32.
// cp.async double-buffered. No lambdas; loads inlined.
// Dynamic smem: Ah 2*128*72*2 + Bh 2*64*136*2 + wscr 8*272*4 = 80384 B.
// ---------------------------------------------------------------------------
#define GB_ALD 72
#define GB_BLD 136
#define GB_ABUF (128 * GB_ALD)     // 9216 bf16
#define GB_BBUF (64 * GB_BLD)      // 8704 bf16
#define GB_SMEM ((2 * GB_ABUF + 2 * GB_BBUF) * 2 + 8 * 272 * 4)

#define GB_LOAD_STAGE(buf, k0)                                                  \
    do {                                                                        \
        _Pragma("unroll")                                                       \
        for (int l = 0; l < 4; l++) {                                           \
            int i = tid + l * 256;                                              \
            int r = i >> 3, c8 = i & 7;                                         \
            cp_async16(&Ah[(buf) * GB_ABUF + r * GB_ALD + c8 * 8],              \
                       &A[(size_t)(bm + r) * K + (k0) + c8 * 8]);               \
        }                                                                       \
        _Pragma("unroll")                                                       \
        for (int l = 0; l < 4; l++) {                                           \
            int i = tid + l * 256;                                              \
            int r = i >> 4, c8 = i & 15;                                        \
            cp_async16(&Bh[(buf) * GB_BBUF + r * GB_BLD + c8 * 8],              \
                       &B[(size_t)((k0) + r) * N + bn + c8 * 8]);               \
        }                                                                       \
        cp_commit();                                                            \
    } while (0)

__global__ __launch_bounds__(256)
void gemm_bf16(const __nv_bfloat16* __restrict__ A, const __nv_bfloat16* __restrict__ B,
               __nv_bfloat16* __restrict__ C, int N, int K)
{
    extern __shared__ __nv_bfloat16 sm_gb[];
    __nv_bfloat16* Ah = sm_gb;                       // 2 * 9216
    __nv_bfloat16* Bh = sm_gb + 2 * GB_ABUF;         // 2 * 8704
    float* wscr = reinterpret_cast<float*>(sm_gb + 2 * GB_ABUF + 2 * GB_BBUF);

    const int tid  = threadIdx.x;
    const int warp = tid >> 5;
    const int lane = tid & 31;
    const int wm   = warp >> 2;          // 0..1 -> rows wm*64
    const int wn   = warp & 3;           // 0..3 -> cols wn*32
    const int bm   = blockIdx.y * 128;
    const int bn   = blockIdx.x * 128;

    GB_LOAD_STAGE(0, 0);

    wmma::fragment<wmma::accumulator, 16, 16, 16, float> acc[4][2];
    #pragma unroll
    for (int mi = 0; mi < 4; mi++)
        #pragma unroll
        for (int ni = 0; ni < 2; ni++)
            wmma::fill_fragment(acc[mi][ni], 0.0f);

    const int KT = K / 64;
    for (int t = 0; t < KT; t++) {
        const int cur = t & 1;
        if (t + 1 < KT) {
            GB_LOAD_STAGE(cur ^ 1, (t + 1) * 64);
            cp_wait_1();
        } else {
            cp_wait_all();
        }
        __syncthreads();

        #pragma unroll
        for (int kk = 0; kk < 64; kk += 16) {
            wmma::fragment<wmma::matrix_a, 16, 16, 16, __nv_bfloat16, wmma::row_major> af[4];
            wmma::fragment<wmma::matrix_b, 16, 16, 16, __nv_bfloat16, wmma::row_major> bf[2];
            #pragma unroll
            for (int mi = 0; mi < 4; mi++)
                wmma::load_matrix_sync(af[mi],
                    &Ah[cur * GB_ABUF + (wm * 64 + mi * 16) * GB_ALD + kk], GB_ALD);
            #pragma unroll
            for (int ni = 0; ni < 2; ni++)
                wmma::load_matrix_sync(bf[ni],
                    &Bh[cur * GB_BBUF + kk * GB_BLD + wn * 32 + ni * 16], GB_BLD);
            #pragma unroll
            for (int mi = 0; mi < 4; mi++)
                #pragma unroll
                for (int ni = 0; ni < 2; ni++)
                    wmma::mma_sync(acc[mi][ni], af[mi], bf[ni], acc[mi][ni]);
        }
        __syncthreads();
    }

    // bf16 epilogue via per-warp scratch
    float* wp = &wscr[warp * 272];
    const int srow = lane >> 1;
    const int half = lane & 1;
    #pragma unroll
    for (int mi = 0; mi < 4; mi++)
        #pragma unroll
        for (int ni = 0; ni < 2; ni++) {
            wmma::store_matrix_sync(wp, acc[mi][ni], 16, wmma::mem_row_major);
            __syncwarp();
            const float* sp = &wp[srow * 16 + half * 8];
            uint4 o;
            o.x = pack_bf162(sp[0], sp[1]);
            o.y = pack_bf162(sp[2], sp[3]);
            o.z = pack_bf162(sp[4], sp[5]);
            o.w = pack_bf162(sp[6], sp[7]);
            *reinterpret_cast<uint4*>(
                &C[(size_t)(bm + wm * 64 + mi * 16 + srow) * N
                   + bn + wn * 32 + ni * 16 + half * 8]) = o;
            __syncwarp();
        }
}

// ---------------------------------------------------------------------------
// exp(S) = exp(f @ g^T), per batch — bf16 MMA (m16n16k16).
// 128x128 tile, K=64 in 4 steps. Epilogue: per-warp stage -> bf16 store +
// f32 row-sum partials atomically accumulated into g_rsum.
// f/g come from the combined g_fgh [MTOT][128] buffer (G at column 64).
// ---------------------------------------------------------------------------
#define SE_LDH 72
__global__ __launch_bounds__(256)
void gemm_s_exp()
{
    extern __shared__ uint8_t sm_raw[];
    __nv_bfloat16* Fh = reinterpret_cast<__nv_bfloat16*>(sm_raw);               // 128*72
    __nv_bfloat16* Gh = Fh + 128 * SE_LDH;                                      // 128*72
    float* wscr = reinterpret_cast<float*>(sm_raw + 2 * 128 * SE_LDH * 2);      // 8*272

    const int tid  = threadIdx.x;
    const int warp = tid >> 5;
    const int lane = tid & 31;
    const int wm   = warp >> 2;        // 0..1 -> rows wm*64
    const int wn   = warp & 3;         // 0..3 -> cols wn*32
    const int bm   = blockIdx.y * 128;
    const int bn   = blockIdx.x * 128;
    const int b    = blockIdx.z;

    const __nv_bfloat16* FG = g_fgh + (size_t)b * NPIX * 128;
    __nv_bfloat16* S = g_sh + (size_t)b * NPIX * NPIX;

    // Load F/G tiles: 128 rows x 8 chunks of 8 bf16 each, 4/thread each
    #pragma unroll
    for (int l = 0; l < 4; l++) {
        int i = tid + l * 256;
        int r = i >> 3, c8 = i & 7;
        *reinterpret_cast<uint4*>(&Fh[r * SE_LDH + c8 * 8]) =
            *reinterpret_cast<const uint4*>(&FG[(size_t)(bm + r) * 128 + c8 * 8]);
        *reinterpret_cast<uint4*>(&Gh[r * SE_LDH + c8 * 8]) =
            *reinterpret_cast<const uint4*>(&FG[(size_t)(bn + r) * 128 + 64 + c8 * 8]);
    }
    __syncthreads();

    wmma::fragment<wmma::accumulator, 16, 16, 16, float> acc[4][2];
    #pragma unroll
    for (int mi = 0; mi < 4; mi++)
        #pragma unroll
        for (int ni = 0; ni < 2; ni++)
            wmma::fill_fragment(acc[mi][ni], 0.0f);

    #pragma unroll
    for (int kk = 0; kk < DQ; kk += 16) {
        wmma::fragment<wmma::matrix_a, 16, 16, 16, __nv_bfloat16, wmma::row_major> af[4];
        wmma::fragment<wmma::matrix_b, 16, 16, 16, __nv_bfloat16, wmma::col_major> bf[2];
        #pragma unroll
        for (int mi = 0; mi < 4; mi++)
            wmma::load_matrix_sync(af[mi], &Fh[(wm * 64 + mi * 16) * SE_LDH + kk], SE_LDH);
        #pragma unroll
        for (int ni = 0; ni < 2; ni++)
            wmma::load_matrix_sync(bf[ni], &Gh[(wn * 32 + ni * 16) * SE_LDH + kk], SE_LDH);
        #pragma unroll
        for (int mi = 0; mi < 4; mi++)
            #pragma unroll
            for (int ni = 0; ni < 2; ni++)
                wmma::mma_sync(acc[mi][ni], af[mi], bf[ni], acc[mi][ni]);
    }

    // exp on fragments, then per-warp stage -> bf16 store + rowsum atomics
    const float LOG2E = 1.4426950408889634f;
    #pragma unroll
    for (int mi = 0; mi < 4; mi++)
        #pragma unroll
        for (int ni = 0; ni < 2; ni++)
            #pragma unroll
            for (int e = 0; e < acc[mi][ni].num_elements; e++)
                acc[mi][ni].x[e] = exp2f(acc[mi][ni].x[e] * LOG2E);

    float* wp = &wscr[warp * 272];
    const int srow = lane >> 1;
    const int half = lane & 1;
    #pragma unroll
    for (int mi = 0; mi < 4; mi++) {
        float rpart = 0.0f;
        #pragma unroll
        for (int ni = 0; ni < 2; ni++) {
            wmma::store_matrix_sync(wp, acc[mi][ni], 16, wmma::mem_row_major);
            __syncwarp();
            const float* sp = &wp[srow * 16 + half * 8];
            rpart += sp[0] + sp[1] + sp[2] + sp[3] + sp[4] + sp[5] + sp[6] + sp[7];
            uint4 o;
            o.x = pack_bf162(sp[0], sp[1]);
            o.y = pack_bf162(sp[2], sp[3]);
            o.z = pack_bf162(sp[4], sp[5]);
            o.w = pack_bf162(sp[6], sp[7]);
            *reinterpret_cast<uint4*>(
                &S[(size_t)(bm + wm * 64 + mi * 16 + srow) * NPIX
                   + bn + wn * 32 + ni * 16 + half * 8]) = o;
            __syncwarp();
        }
        rpart += __shfl_xor_sync(0xFFFFFFFFu, rpart, 1);
        if (half == 0)
            atomicAdd(&g_rsum[b * NPIX + bm + wm * 64 + mi * 16 + srow], rpart);
    }
}

// ---------------------------------------------------------------------------
// out = gamma * (P @ V) + x. M-tile 128, N-tile 256, K-tile 64, 512 threads,
// 16 warps (warp tile 32x64). 3-stage cp.async pipeline. Row sums from g_rsum.
// ---------------------------------------------------------------------------
#define PV_ALD 72
#define PV_BLD 264
#define PV_ABUF (128 * PV_ALD)      // bf16 elems per A stage (9216)
#define PV_BBUF (64 * PV_BLD)       // bf16 elems per B stage (16896)
#define PV_TILES (NPIX / 64)        // 64
#define PV_SMEM ((3 * PV_ABUF + 3 * PV_BBUF) * 2 + 16 * 272 * 4)   // 174080

#define PV_LOAD_STAGE(buf, k0)                                                  \
    do {                                                                        \
        _Pragma("unroll")                                                       \
        for (int l = 0; l < 2; l++) {                                           \
            int i = tid + l * 512;                                              \
            int r = i >> 3, c8 = i & 7;                                         \
            cp_async16(&As[(buf) * PV_ABUF + r * PV_ALD + c8 * 8],              \
                       &S[(size_t)(bm + r) * NPIX + (k0) + c8 * 8]);            \
        }                                                                       \
        _Pragma("unroll")                                                       \
        for (int l = 0; l < 4; l++) {                                           \
            int i = tid + l * 512;                                              \
            int r = i >> 5, c8 = i & 31;                                        \
            cp_async16(&Bs[(buf) * PV_BBUF + r * PV_BLD + c8 * 8],              \
                       &V[(size_t)((k0) + r) * CH + cn0 + c8 * 8]);             \
        }                                                                       \
        cp_commit();                                                            \
    } while (0)

__global__ __launch_bounds__(512, 1)
void gemm_pv(const float* __restrict__ x, const float* __restrict__ gam_p,
             float* __restrict__ out)
{
    extern __shared__ __nv_bfloat16 sm_pv[];
    __nv_bfloat16* As = sm_pv;                        // 3 * 9216
    __nv_bfloat16* Bs = sm_pv + 3 * PV_ABUF;          // 3 * 16896
    float* wscr = reinterpret_cast<float*>(sm_pv + 3 * PV_ABUF + 3 * PV_BBUF);

    const int tid  = threadIdx.x;
    const int warp = tid >> 5;
    const int lane = tid & 31;
    const int wm   = warp >> 2;            // 0..3 -> row offset wm*32
    const int wn   = warp & 3;             // 0..3 -> col offset wn*64
    const int bm   = blockIdx.x * 128;
    const int nh   = blockIdx.y;           // 0..1 -> channel half
    const int b    = blockIdx.z;
    const int cn0  = nh * 256;

    const __nv_bfloat16* S = g_sh + (size_t)b * NPIX * NPIX;
    const __nv_bfloat16* V = g_vh + (size_t)b * NPIX * CH;

    // preload stages 0 and 1
    PV_LOAD_STAGE(0, 0);
    PV_LOAD_STAGE(1, 64);
    cp_wait_1();          // stage 0 complete
    __syncthreads();

    wmma::fragment<wmma::accumulator, 16, 16, 16, float> acc[2][4];
    #pragma unroll
    for (int mi = 0; mi < 2; mi++)
        #pragma unroll
        for (int ni = 0; ni < 4; ni++)
            wmma::fill_fragment(acc[mi][ni], 0.0f);

    for (int t = 0; t < PV_TILES; t++) {
        const int cur = t % 3;
        if (t + 2 < PV_TILES)
            PV_LOAD_STAGE((t + 2) % 3, (t + 2) * 64);

        #pragma unroll
        for (int kk = 0; kk < 64; kk += 16) {
            wmma::fragment<wmma::matrix_a, 16, 16, 16, __nv_bfloat16, wmma::row_major> af[2];
            wmma::fragment<wmma::matrix_b, 16, 16, 16, __nv_bfloat16, wmma::row_major> bf[4];
            #pragma unroll
            for (int mi = 0; mi < 2; mi++)
                wmma::load_matrix_sync(af[mi],
                    &As[cur * PV_ABUF + (wm * 32 + mi * 16) * PV_ALD + kk], PV_ALD);
            #pragma unroll
            for (int ni = 0; ni < 4; ni++)
                wmma::load_matrix_sync(bf[ni],
                    &Bs[cur * PV_BBUF + kk * PV_BLD + wn * 64 + ni * 16], PV_BLD);
            #pragma unroll
            for (int mi = 0; mi < 2; mi++)
                #pragma unroll
                for (int ni = 0; ni < 4; ni++)
                    wmma::mma_sync(acc[mi][ni], af[mi], bf[ni], acc[mi][ni]);
        }

        if (t + 1 < PV_TILES) {
            if (t + 2 < PV_TILES) cp_wait_1();
            else                  cp_wait_all();
            __syncthreads();
        }
    }

    // ---- epilogue: per-warp fragment stage -> normalize -> gamma -> +x ----
    __syncthreads();
    const float gam = gam_p[0];
    float* wp = &wscr[warp * 272];
    const int srow = lane >> 1;
    const int half = lane & 1;

    #pragma unroll
    for (int mi = 0; mi < 2; mi++)
        #pragma unroll
        for (int ni = 0; ni < 4; ni++) {
            wmma::store_matrix_sync(wp, acc[mi][ni], 16, wmma::mem_row_major);
            __syncwarp();
            const int r = wm * 32 + mi * 16 + srow;
            const float sc = gam / g_rsum[b * NPIX + bm + r];
            const float* sp = &wp[srow * 16 + half * 8];
            size_t gidx = ((size_t)b * NPIX + bm + r) * CH
                          + cn0 + wn * 64 + ni * 16 + half * 8;
            float4 x1 = *reinterpret_cast<const float4*>(&x[gidx]);
            float4 x2 = *reinterpret_cast<const float4*>(&x[gidx + 4]);
            float4 o1, o2;
            o1.x = sp[0] * sc + x1.x;  o1.y = sp[1] * sc + x1.y;
            o1.z = sp[2] * sc + x1.z;  o1.w = sp[3] * sc + x1.w;
            o2.x = sp[4] * sc + x2.x;  o2.y = sp[5] * sc + x2.y;
            o2.z = sp[6] * sc + x2.z;  o2.w = sp[7] * sc + x2.w;
            *reinterpret_cast<float4*>(&out[gidx])     = o1;
            *reinterpret_cast<float4*>(&out[gidx + 4]) = o2;
            __syncwarp();
        }
}

// ---------------------------------------------------------------------------
extern "C" void kernel_launch(void* const* d_in, const int* in_sizes, int n_in,
                              void* d_out, int out_size)
{
    const float* x     = (const float*)d_in[0];
    const float* wf    = (const float*)d_in[1];
    const float* wg    = (const float*)d_in[2];
    const float* wh    = (const float*)d_in[3];
    const float* gamma = (const float*)d_in[4];
    float* out = (float*)d_out;

    __nv_bfloat16 *pxh, *pwhh, *pwfg, *pfgh, *pvh;
    cudaGetSymbolAddress((void**)&pxh,  g_xh);
    cudaGetSymbolAddress((void**)&pwhh, g_whh);
    cudaGetSymbolAddress((void**)&pwfg, g_wfg);
    cudaGetSymbolAddress((void**)&pfgh, g_fgh);
    cudaGetSymbolAddress((void**)&pvh,  g_vh);

    const int SE_SMEM = 2 * 128 * SE_LDH * 2 + 8 * 272 * 4;   // 45568
    static bool attr_done = false;
    if (!attr_done) {
        cudaFuncSetAttribute(gemm_bf16,  cudaFuncAttributeMaxDynamicSharedMemorySize, GB_SMEM);
        cudaFuncSetAttribute(gemm_s_exp, cudaFuncAttributeMaxDynamicSharedMemorySize, SE_SMEM);
        cudaFuncSetAttribute(gemm_pv,    cudaFuncAttributeMaxDynamicSharedMemorySize, PV_SMEM);
        attr_done = true;
    }

    // prep: conversions + zero rowsum
    cvt_f32_bf16<<<(MTOT * CH) / 4 / 256, 256>>>(x, pxh);
    cvt_f32_bf16<<<(CH * CH) / 4 / 256, 256>>>(wh, pwhh);
    build_wfg<<<(CH * DQ) / 256, 256>>>(wf, wg);
    zero_rsum<<<MTOT / 1024, 1024>>>();

    // [f|g] = x @ [Wf|Wg]   (bf16 tensor cores)
    gemm_bf16<<<dim3(1, MTOT / 128), 256, GB_SMEM>>>(pxh, pwfg, pfgh, 2 * DQ, CH);

    // v = x @ Wh            (bf16 tensor cores)
    gemm_bf16<<<dim3(CH / 128, MTOT / 128), 256, GB_SMEM>>>(pxh, pwhh, pvh, CH, CH);

    // exp(S) = exp(f @ g^T) (bf16 MMA + output, rowsum atomics)
    gemm_s_exp<<<dim3(NPIX / 128, NPIX / 128, BATCH), 256, SE_SMEM>>>();

    // out = gamma * rownorm(exp(S)) @ V + x
    gemm_pv<<<dim3(NPIX / 128, 2, BATCH), 512, PV_SMEM>>>(x, gamma, out);
}

// round 13
// speedup vs baseline: 1.8230x; 1.0142x over previous
#include <cuda_runtime.h>
#include <cuda_bf16.h>
#include <mma.h>
#include <math.h>
#include <stdint.h>

using namespace nvcuda;

#define BATCH 4
#define NPIX  4096
#define CH    512
#define DQ    64
#define MTOT  (BATCH*NPIX)

// Scratch (device globals: the sanctioned no-alloc workaround)
static __device__ __nv_bfloat16  g_xh[(size_t)MTOT * CH];           // bf16 x (16 MB)
static __device__ __nv_bfloat16  g_whh[CH * CH];                    // bf16 Wh
static __device__ __nv_bfloat16  g_wfg[CH * 2 * DQ];                // bf16 [Wf|Wg] 512x128
static __device__ __nv_bfloat16  g_fgh[MTOT * 2 * DQ];              // bf16 [f|g] (4 MB)
static __device__ __nv_bfloat16  g_vh[(size_t)MTOT * CH];           // 16 MB
static __device__ __nv_bfloat16  g_sh[(size_t)BATCH * NPIX * NPIX]; // 128 MB exp(S)
static __device__ float          g_rsum[MTOT];                      // row sums

// ---------------------------------------------------------------------------
// cp.async helpers
// ---------------------------------------------------------------------------
__device__ __forceinline__ void cp_async16(void* smem_dst, const void* gmem_src) {
    uint32_t sa = (uint32_t)__cvta_generic_to_shared(smem_dst);
    asm volatile("cp.async.cg.shared.global [%0], [%1], 16;\n" :: "r"(sa), "l"(gmem_src));
}
__device__ __forceinline__ void cp_commit() {
    asm volatile("cp.async.commit_group;\n");
}
__device__ __forceinline__ void cp_wait_all() {
    asm volatile("cp.async.wait_group 0;\n");
}
__device__ __forceinline__ void cp_wait_1() {
    asm volatile("cp.async.wait_group 1;\n");
}

__device__ __forceinline__ uint32_t pack_bf162(float lo, float hi) {
    __nv_bfloat162 h = __floats2bfloat162_rn(lo, hi);
    return *reinterpret_cast<uint32_t*>(&h);
}

// ---------------------------------------------------------------------------
// small prep kernels
// ---------------------------------------------------------------------------
__global__ void zero_rsum()
{
    g_rsum[blockIdx.x * 1024 + threadIdx.x] = 0.0f;
}

// float -> bf16, 4 elems per thread (n divisible by 256*4)
__global__ void cvt_f32_bf16(const float* __restrict__ src, __nv_bfloat16* __restrict__ dst)
{
    const size_t i = (size_t)blockIdx.x * 256 + threadIdx.x;
    float4 v = reinterpret_cast<const float4*>(src)[i];
    uint2 o;
    o.x = pack_bf162(v.x, v.y);
    o.y = pack_bf162(v.z, v.w);
    reinterpret_cast<uint2*>(dst)[i] = o;
}

// build Wfg[512][128] = [Wf | Wg] in bf16 (device-side symbol access)
__global__ void build_wfg(const float* __restrict__ wf, const float* __restrict__ wg)
{
    const int i = blockIdx.x * 256 + threadIdx.x;   // 0 .. 512*64-1
    const int r = i >> 6, c = i & 63;
    g_wfg[r * 128 + c]      = __float2bfloat16(wf[r * 64 + c]);
    g_wfg[r * 128 + 64 + c] = __float2bfloat16(wg[r * 64 + c]);
}

// ---------------------------------------------------------------------------
// Generic bf16 GEMM: C[M,N] = A[M,K] @ B[K,N], all bf16, fp32 accum.
// Block tile 128x128, K-tile 64, 256 threads, 8 warps (2x4), warp tile 64x32.
// cp.async double-buffered.
// ---------------------------------------------------------------------------
#define GB_ALD 72
#define GB_BLD 136
#define GB_ABUF (128 * GB_ALD)     // 9216 bf16
#define GB_BBUF (64 * GB_BLD)      // 8704 bf16
#define GB_SMEM ((2 * GB_ABUF + 2 * GB_BBUF) * 2 + 8 * 272 * 4)

#define GB_LOAD_STAGE(buf, k0)                                                  \
    do {                                                                        \
        _Pragma("unroll")                                                       \
        for (int l = 0; l < 4; l++) {                                           \
            int i = tid + l * 256;                                              \
            int r = i >> 3, c8 = i & 7;                                         \
            cp_async16(&Ah[(buf) * GB_ABUF + r * GB_ALD + c8 * 8],              \
                       &A[(size_t)(bm + r) * K + (k0) + c8 * 8]);               \
        }                                                                       \
        _Pragma("unroll")                                                       \
        for (int l = 0; l < 4; l++) {                                           \
            int i = tid + l * 256;                                              \
            int r = i >> 4, c8 = i & 15;                                        \
            cp_async16(&Bh[(buf) * GB_BBUF + r * GB_BLD + c8 * 8],              \
                       &B[(size_t)((k0) + r) * N + bn + c8 * 8]);               \
        }                                                                       \
        cp_commit();                                                            \
    } while (0)

__global__ __launch_bounds__(256)
void gemm_bf16(const __nv_bfloat16* __restrict__ A, const __nv_bfloat16* __restrict__ B,
               __nv_bfloat16* __restrict__ C, int N, int K)
{
    extern __shared__ __nv_bfloat16 sm_gb[];
    __nv_bfloat16* Ah = sm_gb;                       // 2 * 9216
    __nv_bfloat16* Bh = sm_gb + 2 * GB_ABUF;         // 2 * 8704
    float* wscr = reinterpret_cast<float*>(sm_gb + 2 * GB_ABUF + 2 * GB_BBUF);

    const int tid  = threadIdx.x;
    const int warp = tid >> 5;
    const int lane = tid & 31;
    const int wm   = warp >> 2;          // 0..1 -> rows wm*64
    const int wn   = warp & 3;           // 0..3 -> cols wn*32
    const int bm   = blockIdx.y * 128;
    const int bn   = blockIdx.x * 128;

    GB_LOAD_STAGE(0, 0);

    wmma::fragment<wmma::accumulator, 16, 16, 16, float> acc[4][2];
    #pragma unroll
    for (int mi = 0; mi < 4; mi++)
        #pragma unroll
        for (int ni = 0; ni < 2; ni++)
            wmma::fill_fragment(acc[mi][ni], 0.0f);

    const int KT = K / 64;
    for (int t = 0; t < KT; t++) {
        const int cur = t & 1;
        if (t + 1 < KT) {
            GB_LOAD_STAGE(cur ^ 1, (t + 1) * 64);
            cp_wait_1();
        } else {
            cp_wait_all();
        }
        __syncthreads();

        #pragma unroll
        for (int kk = 0; kk < 64; kk += 16) {
            wmma::fragment<wmma::matrix_a, 16, 16, 16, __nv_bfloat16, wmma::row_major> af[4];
            wmma::fragment<wmma::matrix_b, 16, 16, 16, __nv_bfloat16, wmma::row_major> bf[2];
            #pragma unroll
            for (int mi = 0; mi < 4; mi++)
                wmma::load_matrix_sync(af[mi],
                    &Ah[cur * GB_ABUF + (wm * 64 + mi * 16) * GB_ALD + kk], GB_ALD);
            #pragma unroll
            for (int ni = 0; ni < 2; ni++)
                wmma::load_matrix_sync(bf[ni],
                    &Bh[cur * GB_BBUF + kk * GB_BLD + wn * 32 + ni * 16], GB_BLD);
            #pragma unroll
            for (int mi = 0; mi < 4; mi++)
                #pragma unroll
                for (int ni = 0; ni < 2; ni++)
                    wmma::mma_sync(acc[mi][ni], af[mi], bf[ni], acc[mi][ni]);
        }
        __syncthreads();
    }

    // bf16 epilogue via per-warp scratch
    float* wp = &wscr[warp * 272];
    const int srow = lane >> 1;
    const int half = lane & 1;
    #pragma unroll
    for (int mi = 0; mi < 4; mi++)
        #pragma unroll
        for (int ni = 0; ni < 2; ni++) {
            wmma::store_matrix_sync(wp, acc[mi][ni], 16, wmma::mem_row_major);
            __syncwarp();
            const float* sp = &wp[srow * 16 + half * 8];
            uint4 o;
            o.x = pack_bf162(sp[0], sp[1]);
            o.y = pack_bf162(sp[2], sp[3]);
            o.z = pack_bf162(sp[4], sp[5]);
            o.w = pack_bf162(sp[6], sp[7]);
            *reinterpret_cast<uint4*>(
                &C[(size_t)(bm + wm * 64 + mi * 16 + srow) * N
                   + bn + wn * 32 + ni * 16 + half * 8]) = o;
            __syncwarp();
        }
}

// ---------------------------------------------------------------------------
// exp(S) = exp(f @ g^T), per batch — bf16 MMA (m16n16k16).
// 128x128 tile, K=64 in 4 steps. Epilogue: per-warp stage -> bf16 store +
// f32 row-sum partials atomically accumulated into g_rsum.
// ---------------------------------------------------------------------------
#define SE_LDH 72
__global__ __launch_bounds__(256)
void gemm_s_exp()
{
    extern __shared__ uint8_t sm_raw[];
    __nv_bfloat16* Fh = reinterpret_cast<__nv_bfloat16*>(sm_raw);               // 128*72
    __nv_bfloat16* Gh = Fh + 128 * SE_LDH;                                      // 128*72
    float* wscr = reinterpret_cast<float*>(sm_raw + 2 * 128 * SE_LDH * 2);      // 8*272

    const int tid  = threadIdx.x;
    const int warp = tid >> 5;
    const int lane = tid & 31;
    const int wm   = warp >> 2;        // 0..1 -> rows wm*64
    const int wn   = warp & 3;         // 0..3 -> cols wn*32
    const int bm   = blockIdx.y * 128;
    const int bn   = blockIdx.x * 128;
    const int b    = blockIdx.z;

    const __nv_bfloat16* FG = g_fgh + (size_t)b * NPIX * 128;
    __nv_bfloat16* S = g_sh + (size_t)b * NPIX * NPIX;

    #pragma unroll
    for (int l = 0; l < 4; l++) {
        int i = tid + l * 256;
        int r = i >> 3, c8 = i & 7;
        *reinterpret_cast<uint4*>(&Fh[r * SE_LDH + c8 * 8]) =
            *reinterpret_cast<const uint4*>(&FG[(size_t)(bm + r) * 128 + c8 * 8]);
        *reinterpret_cast<uint4*>(&Gh[r * SE_LDH + c8 * 8]) =
            *reinterpret_cast<const uint4*>(&FG[(size_t)(bn + r) * 128 + 64 + c8 * 8]);
    }
    __syncthreads();

    wmma::fragment<wmma::accumulator, 16, 16, 16, float> acc[4][2];
    #pragma unroll
    for (int mi = 0; mi < 4; mi++)
        #pragma unroll
        for (int ni = 0; ni < 2; ni++)
            wmma::fill_fragment(acc[mi][ni], 0.0f);

    #pragma unroll
    for (int kk = 0; kk < DQ; kk += 16) {
        wmma::fragment<wmma::matrix_a, 16, 16, 16, __nv_bfloat16, wmma::row_major> af[4];
        wmma::fragment<wmma::matrix_b, 16, 16, 16, __nv_bfloat16, wmma::col_major> bf[2];
        #pragma unroll
        for (int mi = 0; mi < 4; mi++)
            wmma::load_matrix_sync(af[mi], &Fh[(wm * 64 + mi * 16) * SE_LDH + kk], SE_LDH);
        #pragma unroll
        for (int ni = 0; ni < 2; ni++)
            wmma::load_matrix_sync(bf[ni], &Gh[(wn * 32 + ni * 16) * SE_LDH + kk], SE_LDH);
        #pragma unroll
        for (int mi = 0; mi < 4; mi++)
            #pragma unroll
            for (int ni = 0; ni < 2; ni++)
                wmma::mma_sync(acc[mi][ni], af[mi], bf[ni], acc[mi][ni]);
    }

    // exp on fragments, then per-warp stage -> bf16 store + rowsum atomics
    const float LOG2E = 1.4426950408889634f;
    #pragma unroll
    for (int mi = 0; mi < 4; mi++)
        #pragma unroll
        for (int ni = 0; ni < 2; ni++)
            #pragma unroll
            for (int e = 0; e < acc[mi][ni].num_elements; e++)
                acc[mi][ni].x[e] = exp2f(acc[mi][ni].x[e] * LOG2E);

    float* wp = &wscr[warp * 272];
    const int srow = lane >> 1;
    const int half = lane & 1;
    #pragma unroll
    for (int mi = 0; mi < 4; mi++) {
        float rpart = 0.0f;
        #pragma unroll
        for (int ni = 0; ni < 2; ni++) {
            wmma::store_matrix_sync(wp, acc[mi][ni], 16, wmma::mem_row_major);
            __syncwarp();
            const float* sp = &wp[srow * 16 + half * 8];
            rpart += sp[0] + sp[1] + sp[2] + sp[3] + sp[4] + sp[5] + sp[6] + sp[7];
            uint4 o;
            o.x = pack_bf162(sp[0], sp[1]);
            o.y = pack_bf162(sp[2], sp[3]);
            o.z = pack_bf162(sp[4], sp[5]);
            o.w = pack_bf162(sp[6], sp[7]);
            *reinterpret_cast<uint4*>(
                &S[(size_t)(bm + wm * 64 + mi * 16 + srow) * NPIX
                   + bn + wn * 32 + ni * 16 + half * 8]) = o;
            __syncwarp();
        }
        rpart += __shfl_xor_sync(0xFFFFFFFFu, rpart, 1);
        if (half == 0)
            atomicAdd(&g_rsum[b * NPIX + bm + wm * 64 + mi * 16 + srow], rpart);
    }
}

// ---------------------------------------------------------------------------
// out = gamma * (P @ V) + x. M-tile 128, N-tile 256, K-tile 64, 512 threads,
// 16 warps (warp tile 32x64). 3-stage cp.async pipeline. Row sums from g_rsum.
// ---------------------------------------------------------------------------
#define PV_ALD 72
#define PV_BLD 264
#define PV_ABUF (128 * PV_ALD)      // bf16 elems per A stage (9216)
#define PV_BBUF (64 * PV_BLD)       // bf16 elems per B stage (16896)
#define PV_TILES (NPIX / 64)        // 64
#define PV_SMEM ((3 * PV_ABUF + 3 * PV_BBUF) * 2 + 16 * 272 * 4)   // 174080

#define PV_LOAD_STAGE(buf, k0)                                                  \
    do {                                                                        \
        _Pragma("unroll")                                                       \
        for (int l = 0; l < 2; l++) {                                           \
            int i = tid + l * 512;                                              \
            int r = i >> 3, c8 = i & 7;                                         \
            cp_async16(&As[(buf) * PV_ABUF + r * PV_ALD + c8 * 8],              \
                       &S[(size_t)(bm + r) * NPIX + (k0) + c8 * 8]);            \
        }                                                                       \
        _Pragma("unroll")                                                       \
        for (int l = 0; l < 4; l++) {                                           \
            int i = tid + l * 512;                                              \
            int r = i >> 5, c8 = i & 31;                                        \
            cp_async16(&Bs[(buf) * PV_BBUF + r * PV_BLD + c8 * 8],              \
                       &V[(size_t)((k0) + r) * CH + cn0 + c8 * 8]);             \
        }                                                                       \
        cp_commit();                                                            \
    } while (0)

__global__ __launch_bounds__(512, 1)
void gemm_pv(const float* __restrict__ x, const float* __restrict__ gam_p,
             float* __restrict__ out)
{
    extern __shared__ __nv_bfloat16 sm_pv[];
    __nv_bfloat16* As = sm_pv;                        // 3 * 9216
    __nv_bfloat16* Bs = sm_pv + 3 * PV_ABUF;          // 3 * 16896
    float* wscr = reinterpret_cast<float*>(sm_pv + 3 * PV_ABUF + 3 * PV_BBUF);

    const int tid  = threadIdx.x;
    const int warp = tid >> 5;
    const int lane = tid & 31;
    const int wm   = warp >> 2;            // 0..3 -> row offset wm*32
    const int wn   = warp & 3;             // 0..3 -> col offset wn*64
    const int bm   = blockIdx.x * 128;
    const int nh   = blockIdx.y;           // 0..1 -> channel half
    const int b    = blockIdx.z;
    const int cn0  = nh * 256;

    const __nv_bfloat16* S = g_sh + (size_t)b * NPIX * NPIX;
    const __nv_bfloat16* V = g_vh + (size_t)b * NPIX * CH;

    // preload stages 0 and 1
    PV_LOAD_STAGE(0, 0);
    PV_LOAD_STAGE(1, 64);
    cp_wait_1();          // stage 0 complete
    __syncthreads();

    wmma::fragment<wmma::accumulator, 16, 16, 16, float> acc[2][4];
    #pragma unroll
    for (int mi = 0; mi < 2; mi++)
        #pragma unroll
        for (int ni = 0; ni < 4; ni++)
            wmma::fill_fragment(acc[mi][ni], 0.0f);

    for (int t = 0; t < PV_TILES; t++) {
        const int cur = t % 3;
        if (t + 2 < PV_TILES)
            PV_LOAD_STAGE((t + 2) % 3, (t + 2) * 64);

        #pragma unroll
        for (int kk = 0; kk < 64; kk += 16) {
            wmma::fragment<wmma::matrix_a, 16, 16, 16, __nv_bfloat16, wmma::row_major> af[2];
            wmma::fragment<wmma::matrix_b, 16, 16, 16, __nv_bfloat16, wmma::row_major> bf[4];
            #pragma unroll
            for (int mi = 0; mi < 2; mi++)
                wmma::load_matrix_sync(af[mi],
                    &As[cur * PV_ABUF + (wm * 32 + mi * 16) * PV_ALD + kk], PV_ALD);
            #pragma unroll
            for (int ni = 0; ni < 4; ni++)
                wmma::load_matrix_sync(bf[ni],
                    &Bs[cur * PV_BBUF + kk * PV_BLD + wn * 64 + ni * 16], PV_BLD);
            #pragma unroll
            for (int mi = 0; mi < 2; mi++)
                #pragma unroll
                for (int ni = 0; ni < 4; ni++)
                    wmma::mma_sync(acc[mi][ni], af[mi], bf[ni], acc[mi][ni]);
        }

        if (t + 1 < PV_TILES) {
            if (t + 2 < PV_TILES) cp_wait_1();
            else                  cp_wait_all();
            __syncthreads();
        }
    }

    // ---- epilogue: per-warp fragment stage -> normalize -> gamma -> +x ----
    __syncthreads();
    const float gam = gam_p[0];
    float* wp = &wscr[warp * 272];
    const int srow = lane >> 1;
    const int half = lane & 1;

    #pragma unroll
    for (int mi = 0; mi < 2; mi++)
        #pragma unroll
        for (int ni = 0; ni < 4; ni++) {
            wmma::store_matrix_sync(wp, acc[mi][ni], 16, wmma::mem_row_major);
            __syncwarp();
            const int r = wm * 32 + mi * 16 + srow;
            const float sc = gam / g_rsum[b * NPIX + bm + r];
            const float* sp = &wp[srow * 16 + half * 8];
            size_t gidx = ((size_t)b * NPIX + bm + r) * CH
                          + cn0 + wn * 64 + ni * 16 + half * 8;
            float4 x1 = *reinterpret_cast<const float4*>(&x[gidx]);
            float4 x2 = *reinterpret_cast<const float4*>(&x[gidx + 4]);
            float4 o1, o2;
            o1.x = sp[0] * sc + x1.x;  o1.y = sp[1] * sc + x1.y;
            o1.z = sp[2] * sc + x1.z;  o1.w = sp[3] * sc + x1.w;
            o2.x = sp[4] * sc + x2.x;  o2.y = sp[5] * sc + x2.y;
            o2.z = sp[6] * sc + x2.z;  o2.w = sp[7] * sc + x2.w;
            *reinterpret_cast<float4*>(&out[gidx])     = o1;
            *reinterpret_cast<float4*>(&out[gidx + 4]) = o2;
            __syncwarp();
        }
}

// ---------------------------------------------------------------------------
extern "C" void kernel_launch(void* const* d_in, const int* in_sizes, int n_in,
                              void* d_out, int out_size)
{
    const float* x     = (const float*)d_in[0];
    const float* wf    = (const float*)d_in[1];
    const float* wg    = (const float*)d_in[2];
    const float* wh    = (const float*)d_in[3];
    const float* gamma = (const float*)d_in[4];
    float* out = (float*)d_out;

    __nv_bfloat16 *pxh, *pwhh, *pwfg, *pfgh, *pvh;
    cudaGetSymbolAddress((void**)&pxh,  g_xh);
    cudaGetSymbolAddress((void**)&pwhh, g_whh);
    cudaGetSymbolAddress((void**)&pwfg, g_wfg);
    cudaGetSymbolAddress((void**)&pfgh, g_fgh);
    cudaGetSymbolAddress((void**)&pvh,  g_vh);

    static cudaStream_t s2 = nullptr;
    static cudaEvent_t evX = nullptr, evV = nullptr;
    static bool attr_done = false;
    if (!attr_done) {
        cudaFuncSetAttribute(gemm_bf16,  cudaFuncAttributeMaxDynamicSharedMemorySize, GB_SMEM);
        cudaFuncSetAttribute(gemm_s_exp, cudaFuncAttributeMaxDynamicSharedMemorySize,
                             2 * 128 * SE_LDH * 2 + 8 * 272 * 4);
        cudaFuncSetAttribute(gemm_pv,    cudaFuncAttributeMaxDynamicSharedMemorySize, PV_SMEM);
        cudaStreamCreateWithFlags(&s2, cudaStreamNonBlocking);
        cudaEventCreateWithFlags(&evX, cudaEventDisableTiming);
        cudaEventCreateWithFlags(&evV, cudaEventDisableTiming);
        attr_done = true;
    }
    const int SE_SMEM = 2 * 128 * SE_LDH * 2 + 8 * 272 * 4;   // 45568

    // ---- main stream: x conversion, then fork ----
    cvt_f32_bf16<<<(MTOT * CH) / 4 / 256, 256>>>(x, pxh);
    cudaEventRecord(evX, 0);

    // ---- side stream: Wh conversion + V GEMM (depends only on x, Wh) ----
    cudaStreamWaitEvent(s2, evX, 0);
    cvt_f32_bf16<<<(CH * CH) / 4 / 256, 256, 0, s2>>>(wh, pwhh);
    gemm_bf16<<<dim3(CH / 128, MTOT / 128), 256, GB_SMEM, s2>>>(pxh, pwhh, pvh, CH, CH);
    cudaEventRecord(evV, s2);

    // ---- main stream: fg chain ----
    build_wfg<<<(CH * DQ) / 256, 256>>>(wf, wg);
    zero_rsum<<<MTOT / 1024, 1024>>>();

    // [f|g] = x @ [Wf|Wg]
    gemm_bf16<<<dim3(1, MTOT / 128), 256, GB_SMEM>>>(pxh, pwfg, pfgh, 2 * DQ, CH);

    // exp(S) = exp(f @ g^T) with rowsum atomics
    gemm_s_exp<<<dim3(NPIX / 128, NPIX / 128, BATCH), 256, SE_SMEM>>>();

    // ---- join: PV needs both S and V ----
    cudaStreamWaitEvent(0, evV, 0);
    gemm_pv<<<dim3(NPIX / 128, 2, BATCH), 512, PV_SMEM>>>(x, gamma, out);
}

// round 14
// speedup vs baseline: 2.0505x; 1.1248x over previous
#include <cuda_runtime.h>
#include <cuda_bf16.h>
#include <mma.h>
#include <math.h>
#include <stdint.h>

using namespace nvcuda;

#define BATCH 4
#define NPIX  4096
#define CH    512
#define DQ    64
#define MTOT  (BATCH*NPIX)

// Scratch (device globals: the sanctioned no-alloc workaround)
static __device__ __nv_bfloat16  g_xh[(size_t)MTOT * CH];           // bf16 x (16 MB)
static __device__ __nv_bfloat16  g_whh[CH * CH];                    // bf16 Wh
static __device__ __nv_bfloat16  g_wfg[CH * 2 * DQ];                // bf16 [Wf|Wg] 512x128
static __device__ __nv_bfloat16  g_fgh[MTOT * 2 * DQ];              // bf16 [f|g] (4 MB)
static __device__ __nv_bfloat16  g_vh[(size_t)MTOT * CH];           // 16 MB
static __device__ __nv_bfloat16  g_sh[(size_t)BATCH * NPIX * NPIX]; // 128 MB exp(S)
static __device__ float          g_rsum[MTOT];                      // row sums

// ---------------------------------------------------------------------------
// cp.async helpers
// ---------------------------------------------------------------------------
__device__ __forceinline__ void cp_async16(void* smem_dst, const void* gmem_src) {
    uint32_t sa = (uint32_t)__cvta_generic_to_shared(smem_dst);
    asm volatile("cp.async.cg.shared.global [%0], [%1], 16;\n" :: "r"(sa), "l"(gmem_src));
}
__device__ __forceinline__ void cp_commit() {
    asm volatile("cp.async.commit_group;\n");
}
__device__ __forceinline__ void cp_wait_all() {
    asm volatile("cp.async.wait_group 0;\n");
}
__device__ __forceinline__ void cp_wait_1() {
    asm volatile("cp.async.wait_group 1;\n");
}

__device__ __forceinline__ uint32_t pack_bf162(float lo, float hi) {
    __nv_bfloat162 h = __floats2bfloat162_rn(lo, hi);
    return *reinterpret_cast<uint32_t*>(&h);
}

// ---------------------------------------------------------------------------
// small prep kernels
// ---------------------------------------------------------------------------
__global__ void zero_rsum()
{
    g_rsum[blockIdx.x * 1024 + threadIdx.x] = 0.0f;
}

// float -> bf16, 4 elems per thread (n divisible by 256*4)
__global__ void cvt_f32_bf16(const float* __restrict__ src, __nv_bfloat16* __restrict__ dst)
{
    const size_t i = (size_t)blockIdx.x * 256 + threadIdx.x;
    float4 v = reinterpret_cast<const float4*>(src)[i];
    uint2 o;
    o.x = pack_bf162(v.x, v.y);
    o.y = pack_bf162(v.z, v.w);
    reinterpret_cast<uint2*>(dst)[i] = o;
}

// build Wfg[512][128] = [Wf | Wg] in bf16 (device-side symbol access)
__global__ void build_wfg(const float* __restrict__ wf, const float* __restrict__ wg)
{
    const int i = blockIdx.x * 256 + threadIdx.x;   // 0 .. 512*64-1
    const int r = i >> 6, c = i & 63;
    g_wfg[r * 128 + c]      = __float2bfloat16(wf[r * 64 + c]);
    g_wfg[r * 128 + 64 + c] = __float2bfloat16(wg[r * 64 + c]);
}

// ---------------------------------------------------------------------------
// Generic bf16 GEMM: C[M,N] = A[M,K] @ B[K,N], all bf16, fp32 accum.
// Block tile 128x128, K-tile 64, 256 threads, 8 warps (2x4), warp tile 64x32.
// cp.async double-buffered.
// ---------------------------------------------------------------------------
#define GB_ALD 72
#define GB_BLD 136
#define GB_ABUF (128 * GB_ALD)     // 9216 bf16
#define GB_BBUF (64 * GB_BLD)      // 8704 bf16
#define GB_SMEM ((2 * GB_ABUF + 2 * GB_BBUF) * 2 + 8 * 272 * 4)

#define GB_LOAD_STAGE(buf, k0)                                                  \
    do {                                                                        \
        _Pragma("unroll")                                                       \
        for (int l = 0; l < 4; l++) {                                           \
            int i = tid + l * 256;                                              \
            int r = i >> 3, c8 = i & 7;                                         \
            cp_async16(&Ah[(buf) * GB_ABUF + r * GB_ALD + c8 * 8],              \
                       &A[(size_t)(bm + r) * K + (k0) + c8 * 8]);               \
        }                                                                       \
        _Pragma("unroll")                                                       \
        for (int l = 0; l < 4; l++) {                                           \
            int i = tid + l * 256;                                              \
            int r = i >> 4, c8 = i & 15;                                        \
            cp_async16(&Bh[(buf) * GB_BBUF + r * GB_BLD + c8 * 8],              \
                       &B[(size_t)((k0) + r) * N + bn + c8 * 8]);               \
        }                                                                       \
        cp_commit();                                                            \
    } while (0)

__global__ __launch_bounds__(256)
void gemm_bf16(const __nv_bfloat16* __restrict__ A, const __nv_bfloat16* __restrict__ B,
               __nv_bfloat16* __restrict__ C, int N, int K)
{
    extern __shared__ __nv_bfloat16 sm_gb[];
    __nv_bfloat16* Ah = sm_gb;                       // 2 * 9216
    __nv_bfloat16* Bh = sm_gb + 2 * GB_ABUF;         // 2 * 8704
    float* wscr = reinterpret_cast<float*>(sm_gb + 2 * GB_ABUF + 2 * GB_BBUF);

    const int tid  = threadIdx.x;
    const int warp = tid >> 5;
    const int lane = tid & 31;
    const int wm   = warp >> 2;          // 0..1 -> rows wm*64
    const int wn   = warp & 3;           // 0..3 -> cols wn*32
    const int bm   = blockIdx.y * 128;
    const int bn   = blockIdx.x * 128;

    GB_LOAD_STAGE(0, 0);

    wmma::fragment<wmma::accumulator, 16, 16, 16, float> acc[4][2];
    #pragma unroll
    for (int mi = 0; mi < 4; mi++)
        #pragma unroll
        for (int ni = 0; ni < 2; ni++)
            wmma::fill_fragment(acc[mi][ni], 0.0f);

    const int KT = K / 64;
    for (int t = 0; t < KT; t++) {
        const int cur = t & 1;
        if (t + 1 < KT) {
            GB_LOAD_STAGE(cur ^ 1, (t + 1) * 64);
            cp_wait_1();
        } else {
            cp_wait_all();
        }
        __syncthreads();

        #pragma unroll
        for (int kk = 0; kk < 64; kk += 16) {
            wmma::fragment<wmma::matrix_a, 16, 16, 16, __nv_bfloat16, wmma::row_major> af[4];
            wmma::fragment<wmma::matrix_b, 16, 16, 16, __nv_bfloat16, wmma::row_major> bf[2];
            #pragma unroll
            for (int mi = 0; mi < 4; mi++)
                wmma::load_matrix_sync(af[mi],
                    &Ah[cur * GB_ABUF + (wm * 64 + mi * 16) * GB_ALD + kk], GB_ALD);
            #pragma unroll
            for (int ni = 0; ni < 2; ni++)
                wmma::load_matrix_sync(bf[ni],
                    &Bh[cur * GB_BBUF + kk * GB_BLD + wn * 32 + ni * 16], GB_BLD);
            #pragma unroll
            for (int mi = 0; mi < 4; mi++)
                #pragma unroll
                for (int ni = 0; ni < 2; ni++)
                    wmma::mma_sync(acc[mi][ni], af[mi], bf[ni], acc[mi][ni]);
        }
        __syncthreads();
    }

    // bf16 epilogue via per-warp scratch
    float* wp = &wscr[warp * 272];
    const int srow = lane >> 1;
    const int half = lane & 1;
    #pragma unroll
    for (int mi = 0; mi < 4; mi++)
        #pragma unroll
        for (int ni = 0; ni < 2; ni++) {
            wmma::store_matrix_sync(wp, acc[mi][ni], 16, wmma::mem_row_major);
            __syncwarp();
            const float* sp = &wp[srow * 16 + half * 8];
            uint4 o;
            o.x = pack_bf162(sp[0], sp[1]);
            o.y = pack_bf162(sp[2], sp[3]);
            o.z = pack_bf162(sp[4], sp[5]);
            o.w = pack_bf162(sp[6], sp[7]);
            *reinterpret_cast<uint4*>(
                &C[(size_t)(bm + wm * 64 + mi * 16 + srow) * N
                   + bn + wn * 32 + ni * 16 + half * 8]) = o;
            __syncwarp();
        }
}

// ---------------------------------------------------------------------------
// exp(S) = exp(f @ g^T), per batch — bf16 MMA (m16n16k16).
// 128x128 tile, K=64 in 4 steps. Epilogue: per-warp stage -> bf16 store +
// f32 row-sum partials atomically accumulated into g_rsum.
// ---------------------------------------------------------------------------
#define SE_LDH 72
__global__ __launch_bounds__(256)
void gemm_s_exp()
{
    extern __shared__ uint8_t sm_raw[];
    __nv_bfloat16* Fh = reinterpret_cast<__nv_bfloat16*>(sm_raw);               // 128*72
    __nv_bfloat16* Gh = Fh + 128 * SE_LDH;                                      // 128*72
    float* wscr = reinterpret_cast<float*>(sm_raw + 2 * 128 * SE_LDH * 2);      // 8*272

    const int tid  = threadIdx.x;
    const int warp = tid >> 5;
    const int lane = tid & 31;
    const int wm   = warp >> 2;        // 0..1 -> rows wm*64
    const int wn   = warp & 3;         // 0..3 -> cols wn*32
    const int bm   = blockIdx.y * 128;
    const int bn   = blockIdx.x * 128;
    const int b    = blockIdx.z;

    const __nv_bfloat16* FG = g_fgh + (size_t)b * NPIX * 128;
    __nv_bfloat16* S = g_sh + (size_t)b * NPIX * NPIX;

    #pragma unroll
    for (int l = 0; l < 4; l++) {
        int i = tid + l * 256;
        int r = i >> 3, c8 = i & 7;
        *reinterpret_cast<uint4*>(&Fh[r * SE_LDH + c8 * 8]) =
            *reinterpret_cast<const uint4*>(&FG[(size_t)(bm + r) * 128 + c8 * 8]);
        *reinterpret_cast<uint4*>(&Gh[r * SE_LDH + c8 * 8]) =
            *reinterpret_cast<const uint4*>(&FG[(size_t)(bn + r) * 128 + 64 + c8 * 8]);
    }
    __syncthreads();

    wmma::fragment<wmma::accumulator, 16, 16, 16, float> acc[4][2];
    #pragma unroll
    for (int mi = 0; mi < 4; mi++)
        #pragma unroll
        for (int ni = 0; ni < 2; ni++)
            wmma::fill_fragment(acc[mi][ni], 0.0f);

    #pragma unroll
    for (int kk = 0; kk < DQ; kk += 16) {
        wmma::fragment<wmma::matrix_a, 16, 16, 16, __nv_bfloat16, wmma::row_major> af[4];
        wmma::fragment<wmma::matrix_b, 16, 16, 16, __nv_bfloat16, wmma::col_major> bf[2];
        #pragma unroll
        for (int mi = 0; mi < 4; mi++)
            wmma::load_matrix_sync(af[mi], &Fh[(wm * 64 + mi * 16) * SE_LDH + kk], SE_LDH);
        #pragma unroll
        for (int ni = 0; ni < 2; ni++)
            wmma::load_matrix_sync(bf[ni], &Gh[(wn * 32 + ni * 16) * SE_LDH + kk], SE_LDH);
        #pragma unroll
        for (int mi = 0; mi < 4; mi++)
            #pragma unroll
            for (int ni = 0; ni < 2; ni++)
                wmma::mma_sync(acc[mi][ni], af[mi], bf[ni], acc[mi][ni]);
    }

    // exp on fragments, then per-warp stage -> bf16 store + rowsum atomics
    const float LOG2E = 1.4426950408889634f;
    #pragma unroll
    for (int mi = 0; mi < 4; mi++)
        #pragma unroll
        for (int ni = 0; ni < 2; ni++)
            #pragma unroll
            for (int e = 0; e < acc[mi][ni].num_elements; e++)
                acc[mi][ni].x[e] = exp2f(acc[mi][ni].x[e] * LOG2E);

    float* wp = &wscr[warp * 272];
    const int srow = lane >> 1;
    const int half = lane & 1;
    #pragma unroll
    for (int mi = 0; mi < 4; mi++) {
        float rpart = 0.0f;
        #pragma unroll
        for (int ni = 0; ni < 2; ni++) {
            wmma::store_matrix_sync(wp, acc[mi][ni], 16, wmma::mem_row_major);
            __syncwarp();
            const float* sp = &wp[srow * 16 + half * 8];
            rpart += sp[0] + sp[1] + sp[2] + sp[3] + sp[4] + sp[5] + sp[6] + sp[7];
            uint4 o;
            o.x = pack_bf162(sp[0], sp[1]);
            o.y = pack_bf162(sp[2], sp[3]);
            o.z = pack_bf162(sp[4], sp[5]);
            o.w = pack_bf162(sp[6], sp[7]);
            *reinterpret_cast<uint4*>(
                &S[(size_t)(bm + wm * 64 + mi * 16 + srow) * NPIX
                   + bn + wn * 32 + ni * 16 + half * 8]) = o;
            __syncwarp();
        }
        rpart += __shfl_xor_sync(0xFFFFFFFFu, rpart, 1);
        if (half == 0)
            atomicAdd(&g_rsum[b * NPIX + bm + wm * 64 + mi * 16 + srow], rpart);
    }
}

// ---------------------------------------------------------------------------
// out = gamma * (P @ V) + x. M-tile 128, N-tile 256, K-tile 64.
// 256 threads, 8 warps, warp tile 64x64 (acc 4x4 = 128 regs/thread, no spill
// at 256 threads). 3-stage cp.async pipeline. Row sums from g_rsum.
// ---------------------------------------------------------------------------
#define PV_ALD 72
#define PV_BLD 264
#define PV_ABUF (128 * PV_ALD)      // bf16 elems per A stage (9216)
#define PV_BBUF (64 * PV_BLD)       // bf16 elems per B stage (16896)
#define PV_TILES (NPIX / 64)        // 64
#define PV_SMEM ((3 * PV_ABUF + 3 * PV_BBUF) * 2 + 8 * 272 * 4)    // 165376

#define PV_LOAD_STAGE(buf, k0)                                                  \
    do {                                                                        \
        _Pragma("unroll")                                                       \
        for (int l = 0; l < 4; l++) {                                           \
            int i = tid + l * 256;                                              \
            int r = i >> 3, c8 = i & 7;                                         \
            cp_async16(&As[(buf) * PV_ABUF + r * PV_ALD + c8 * 8],              \
                       &S[(size_t)(bm + r) * NPIX + (k0) + c8 * 8]);            \
        }                                                                       \
        _Pragma("unroll")                                                       \
        for (int l = 0; l < 8; l++) {                                           \
            int i = tid + l * 256;                                              \
            int r = i >> 5, c8 = i & 31;                                        \
            cp_async16(&Bs[(buf) * PV_BBUF + r * PV_BLD + c8 * 8],              \
                       &V[(size_t)((k0) + r) * CH + cn0 + c8 * 8]);             \
        }                                                                       \
        cp_commit();                                                            \
    } while (0)

__global__ __launch_bounds__(256, 1)
void gemm_pv(const float* __restrict__ x, const float* __restrict__ gam_p,
             float* __restrict__ out)
{
    extern __shared__ __nv_bfloat16 sm_pv[];
    __nv_bfloat16* As = sm_pv;                        // 3 * 9216
    __nv_bfloat16* Bs = sm_pv + 3 * PV_ABUF;          // 3 * 16896
    float* wscr = reinterpret_cast<float*>(sm_pv + 3 * PV_ABUF + 3 * PV_BBUF);

    const int tid  = threadIdx.x;
    const int warp = tid >> 5;
    const int lane = tid & 31;
    const int wm   = warp & 1;             // 0..1 -> row offset wm*64
    const int wn   = warp >> 1;            // 0..3 -> col offset wn*64
    const int bm   = blockIdx.x * 128;
    const int nh   = blockIdx.y;           // 0..1 -> channel half
    const int b    = blockIdx.z;
    const int cn0  = nh * 256;

    const __nv_bfloat16* S = g_sh + (size_t)b * NPIX * NPIX;
    const __nv_bfloat16* V = g_vh + (size_t)b * NPIX * CH;

    // preload stages 0 and 1
    PV_LOAD_STAGE(0, 0);
    PV_LOAD_STAGE(1, 64);
    cp_wait_1();          // stage 0 complete
    __syncthreads();

    wmma::fragment<wmma::accumulator, 16, 16, 16, float> acc[4][4];
    #pragma unroll
    for (int mi = 0; mi < 4; mi++)
        #pragma unroll
        for (int ni = 0; ni < 4; ni++)
            wmma::fill_fragment(acc[mi][ni], 0.0f);

    for (int t = 0; t < PV_TILES; t++) {
        const int cur = t % 3;
        if (t + 2 < PV_TILES)
            PV_LOAD_STAGE((t + 2) % 3, (t + 2) * 64);

        #pragma unroll
        for (int kk = 0; kk < 64; kk += 16) {
            wmma::fragment<wmma::matrix_a, 16, 16, 16, __nv_bfloat16, wmma::row_major> af[4];
            wmma::fragment<wmma::matrix_b, 16, 16, 16, __nv_bfloat16, wmma::row_major> bf[4];
            #pragma unroll
            for (int mi = 0; mi < 4; mi++)
                wmma::load_matrix_sync(af[mi],
                    &As[cur * PV_ABUF + (wm * 64 + mi * 16) * PV_ALD + kk], PV_ALD);
            #pragma unroll
            for (int ni = 0; ni < 4; ni++)
                wmma::load_matrix_sync(bf[ni],
                    &Bs[cur * PV_BBUF + kk * PV_BLD + wn * 64 + ni * 16], PV_BLD);
            #pragma unroll
            for (int mi = 0; mi < 4; mi++)
                #pragma unroll
                for (int ni = 0; ni < 4; ni++)
                    wmma::mma_sync(acc[mi][ni], af[mi], bf[ni], acc[mi][ni]);
        }

        if (t + 1 < PV_TILES) {
            if (t + 2 < PV_TILES) cp_wait_1();
            else                  cp_wait_all();
            __syncthreads();
        }
    }

    // ---- epilogue: per-warp fragment stage -> normalize -> gamma -> +x ----
    __syncthreads();
    const float gam = gam_p[0];
    float* wp = &wscr[warp * 272];
    const int srow = lane >> 1;
    const int half = lane & 1;

    #pragma unroll
    for (int mi = 0; mi < 4; mi++)
        #pragma unroll
        for (int ni = 0; ni < 4; ni++) {
            wmma::store_matrix_sync(wp, acc[mi][ni], 16, wmma::mem_row_major);
            __syncwarp();
            const int r = wm * 64 + mi * 16 + srow;
            const float sc = gam / g_rsum[b * NPIX + bm + r];
            const float* sp = &wp[srow * 16 + half * 8];
            size_t gidx = ((size_t)b * NPIX + bm + r) * CH
                          + cn0 + wn * 64 + ni * 16 + half * 8;
            float4 x1 = *reinterpret_cast<const float4*>(&x[gidx]);
            float4 x2 = *reinterpret_cast<const float4*>(&x[gidx + 4]);
            float4 o1, o2;
            o1.x = sp[0] * sc + x1.x;  o1.y = sp[1] * sc + x1.y;
            o1.z = sp[2] * sc + x1.z;  o1.w = sp[3] * sc + x1.w;
            o2.x = sp[4] * sc + x2.x;  o2.y = sp[5] * sc + x2.y;
            o2.z = sp[6] * sc + x2.z;  o2.w = sp[7] * sc + x2.w;
            *reinterpret_cast<float4*>(&out[gidx])     = o1;
            *reinterpret_cast<float4*>(&out[gidx + 4]) = o2;
            __syncwarp();
        }
}

// ---------------------------------------------------------------------------
extern "C" void kernel_launch(void* const* d_in, const int* in_sizes, int n_in,
                              void* d_out, int out_size)
{
    const float* x     = (const float*)d_in[0];
    const float* wf    = (const float*)d_in[1];
    const float* wg    = (const float*)d_in[2];
    const float* wh    = (const float*)d_in[3];
    const float* gamma = (const float*)d_in[4];
    float* out = (float*)d_out;

    __nv_bfloat16 *pxh, *pwhh, *pwfg, *pfgh, *pvh;
    cudaGetSymbolAddress((void**)&pxh,  g_xh);
    cudaGetSymbolAddress((void**)&pwhh, g_whh);
    cudaGetSymbolAddress((void**)&pwfg, g_wfg);
    cudaGetSymbolAddress((void**)&pfgh, g_fgh);
    cudaGetSymbolAddress((void**)&pvh,  g_vh);

    static cudaStream_t s2 = nullptr;
    static cudaEvent_t evX = nullptr, evV = nullptr;
    static bool attr_done = false;
    if (!attr_done) {
        cudaFuncSetAttribute(gemm_bf16,  cudaFuncAttributeMaxDynamicSharedMemorySize, GB_SMEM);
        cudaFuncSetAttribute(gemm_s_exp, cudaFuncAttributeMaxDynamicSharedMemorySize,
                             2 * 128 * SE_LDH * 2 + 8 * 272 * 4);
        cudaFuncSetAttribute(gemm_pv,    cudaFuncAttributeMaxDynamicSharedMemorySize, PV_SMEM);
        cudaStreamCreateWithFlags(&s2, cudaStreamNonBlocking);
        cudaEventCreateWithFlags(&evX, cudaEventDisableTiming);
        cudaEventCreateWithFlags(&evV, cudaEventDisableTiming);
        attr_done = true;
    }
    const int SE_SMEM = 2 * 128 * SE_LDH * 2 + 8 * 272 * 4;   // 45568

    // ---- main stream: x conversion, then fork ----
    cvt_f32_bf16<<<(MTOT * CH) / 4 / 256, 256>>>(x, pxh);
    cudaEventRecord(evX, 0);

    // ---- side stream: Wh conversion + V GEMM (depends only on x, Wh) ----
    cudaStreamWaitEvent(s2, evX, 0);
    cvt_f32_bf16<<<(CH * CH) / 4 / 256, 256, 0, s2>>>(wh, pwhh);
    gemm_bf16<<<dim3(CH / 128, MTOT / 128), 256, GB_SMEM, s2>>>(pxh, pwhh, pvh, CH, CH);
    cudaEventRecord(evV, s2);

    // ---- main stream: fg chain ----
    build_wfg<<<(CH * DQ) / 256, 256>>>(wf, wg);
    zero_rsum<<<MTOT / 1024, 1024>>>();

    // [f|g] = x @ [Wf|Wg]
    gemm_bf16<<<dim3(1, MTOT / 128), 256, GB_SMEM>>>(pxh, pwfg, pfgh, 2 * DQ, CH);

    // exp(S) = exp(f @ g^T) with rowsum atomics
    gemm_s_exp<<<dim3(NPIX / 128, NPIX / 128, BATCH), 256, SE_SMEM>>>();

    // ---- join: PV needs both S and V ----
    cudaStreamWaitEvent(0, evV, 0);
    gemm_pv<<<dim3(NPIX / 128, 2, BATCH), 256, PV_SMEM>>>(x, gamma, out);
}